// round 3
// baseline (speedup 1.0000x reference)
#include <cuda_runtime.h>
#include <cstdint>
#include <cstddef>

#define N_NODES 102400
#define N_EDGES 1638400
#define N_REL   8
#define D0      256
#define D1      128
#define D2      64

// ---------------- scratch (device globals; no allocation allowed) ----------
__device__ __align__(16) float g_xw1[(size_t)N_REL * N_NODES * D1]; // 419 MB
__device__ __align__(16) float g_h1 [(size_t)N_NODES * D1];         // 52 MB
__device__ __align__(16) float g_xw2[(size_t)N_REL * N_NODES * D2]; // 210 MB
__device__ __align__(16) float g_h2 [(size_t)N_NODES * D2];         // 26 MB
__device__ __align__(16) float g_xw3[(size_t)N_REL * N_NODES];      // 3.3 MB

// ---------------- batched per-relation SGEMM -------------------------------
// C[r] = (relu?)A @ B[r],  A:[M,K] row-major, B[r]:[K,N], C[r]:[M,N]
// blockIdx.x tiles M, blockIdx.z = relation. M = N_NODES (divisible by BM).
template<int BM, int BN, int BK, int TM, int TN, int Kdim, int Ndim, bool RELU>
__global__ __launch_bounds__((BM / TM) * (BN / TN))
void rgemm(const float* __restrict__ A, const float* __restrict__ B,
           float* __restrict__ C) {
    constexpr int NT = (BM / TM) * (BN / TN);
    __shared__ float As[BK][BM];
    __shared__ float Bs[BK][BN];

    const int r = blockIdx.z;
    const float* Br = B + (size_t)r * Kdim * Ndim;
    float* Cr = C + (size_t)r * N_NODES * Ndim;

    const int m0  = blockIdx.x * BM;
    const int tid = threadIdx.x;
    const int tx  = tid % (BN / TN);
    const int ty  = tid / (BN / TN);

    float acc[TM][TN];
#pragma unroll
    for (int i = 0; i < TM; i++)
#pragma unroll
        for (int j = 0; j < TN; j++) acc[i][j] = 0.f;

    for (int k0 = 0; k0 < Kdim; k0 += BK) {
        // load A tile (transposed into smem), fuse relu
#pragma unroll
        for (int i = tid; i < BM * BK / 4; i += NT) {
            int row = i / (BK / 4);
            int kc  = (i % (BK / 4)) * 4;
            float4 v = *(const float4*)&A[(size_t)(m0 + row) * Kdim + k0 + kc];
            if (RELU) {
                v.x = fmaxf(v.x, 0.f); v.y = fmaxf(v.y, 0.f);
                v.z = fmaxf(v.z, 0.f); v.w = fmaxf(v.w, 0.f);
            }
            As[kc + 0][row] = v.x; As[kc + 1][row] = v.y;
            As[kc + 2][row] = v.z; As[kc + 3][row] = v.w;
        }
        // load B tile
#pragma unroll
        for (int i = tid; i < BK * BN / 4; i += NT) {
            int row = i / (BN / 4);
            int col = (i % (BN / 4)) * 4;
            *(float4*)&Bs[row][col] =
                *(const float4*)&Br[(size_t)(k0 + row) * Ndim + col];
        }
        __syncthreads();
#pragma unroll
        for (int kk = 0; kk < BK; kk++) {
            float a[TM], b[TN];
#pragma unroll
            for (int i = 0; i < TM; i++) a[i] = As[kk][ty * TM + i];
#pragma unroll
            for (int j = 0; j < TN; j++) b[j] = Bs[kk][tx * TN + j];
#pragma unroll
            for (int i = 0; i < TM; i++)
#pragma unroll
                for (int j = 0; j < TN; j++) acc[i][j] += a[i] * b[j];
        }
        __syncthreads();
    }
#pragma unroll
    for (int i = 0; i < TM; i++) {
        int row = m0 + ty * TM + i;
#pragma unroll
        for (int j = 0; j < TN; j += 4) {
            float4 v = make_float4(acc[i][j], acc[i][j + 1],
                                   acc[i][j + 2], acc[i][j + 3]);
            *(float4*)&Cr[(size_t)row * Ndim + tx * TN + j] = v;
        }
    }
}

// ---------------- layer-3 transform: xw3[r,n] = relu(h2[n]) . W3[r] --------
__global__ void gemm3_kernel(const float* __restrict__ h2,
                             const float* __restrict__ W3,
                             float* __restrict__ xw3) {
    __shared__ float w[N_REL][D2];
    for (int i = threadIdx.x; i < N_REL * D2; i += blockDim.x)
        w[i / D2][i % D2] = W3[i];
    __syncthreads();

    int n = blockIdx.x * blockDim.x + threadIdx.x;
    if (n >= N_NODES) return;

    float acc[N_REL];
#pragma unroll
    for (int r = 0; r < N_REL; r++) acc[r] = 0.f;

    const float4* hp = (const float4*)&h2[(size_t)n * D2];
#pragma unroll
    for (int k4 = 0; k4 < D2 / 4; k4++) {
        float4 v = hp[k4];
        v.x = fmaxf(v.x, 0.f); v.y = fmaxf(v.y, 0.f);
        v.z = fmaxf(v.z, 0.f); v.w = fmaxf(v.w, 0.f);
#pragma unroll
        for (int r = 0; r < N_REL; r++) {
            acc[r] += v.x * w[r][k4 * 4 + 0];
            acc[r] += v.y * w[r][k4 * 4 + 1];
            acc[r] += v.z * w[r][k4 * 4 + 2];
            acc[r] += v.w * w[r][k4 * 4 + 3];
        }
    }
#pragma unroll
    for (int r = 0; r < N_REL; r++)
        xw3[(size_t)r * N_NODES + n] = acc[r];
}

// ---------------- bias init ------------------------------------------------
template<int D>
__global__ void init_bias(float* __restrict__ h, const float* __restrict__ bias) {
    size_t i = (size_t)blockIdx.x * blockDim.x + threadIdx.x;
    if (i < (size_t)N_NODES * D) h[i] = bias[i & (D - 1)];
}

__global__ void init_out(float* __restrict__ out, const float* __restrict__ b3) {
    int i = blockIdx.x * blockDim.x + threadIdx.x;
    if (i < N_NODES) out[i] = b3[0];
}

// ---------------- edge scatter: h[dst] += xw[etype, src] * ew --------------
// One (sub-)warp group of D/4 lanes handles one edge: coalesced float4 gather
// from xw row, 4 scalar atomic adds into h row.
template<int D>
__global__ void edge_scatter(const float* __restrict__ xw,
                             const int* __restrict__ eidx,
                             const float* __restrict__ ew,
                             const int* __restrict__ et,
                             float* __restrict__ h) {
    constexpr int LPE = D / 4;        // lanes per edge
    constexpr int EPW = 32 / LPE;     // edges per warp
    int warp = (blockIdx.x * blockDim.x + threadIdx.x) >> 5;
    int lane = threadIdx.x & 31;
    int e = warp * EPW + lane / LPE;
    if (e >= N_EDGES) return;
    int sub = (lane % LPE) * 4;

    int   src = eidx[e];
    int   dst = eidx[N_EDGES + e];
    int   t   = et[e];
    float w   = ew[e];

    float4 v = *(const float4*)&xw[((size_t)t * N_NODES + (size_t)src) * D + sub];
    float* o = &h[(size_t)dst * D + sub];
    atomicAdd(o + 0, v.x * w);
    atomicAdd(o + 1, v.y * w);
    atomicAdd(o + 2, v.z * w);
    atomicAdd(o + 3, v.w * w);
}

__global__ void edge_scatter1(const float* __restrict__ xw3,
                              const int* __restrict__ eidx,
                              const float* __restrict__ ew,
                              const int* __restrict__ et,
                              float* __restrict__ out) {
    int e = blockIdx.x * blockDim.x + threadIdx.x;
    if (e >= N_EDGES) return;
    int src = eidx[e];
    int dst = eidx[N_EDGES + e];
    int t   = et[e];
    atomicAdd(&out[dst], xw3[(size_t)t * N_NODES + (size_t)src] * ew[e]);
}

// ---------------- launcher --------------------------------------------------
extern "C" void kernel_launch(void* const* d_in, const int* in_sizes, int n_in,
                              void* d_out, int out_size) {
    const float* b_z  = (const float*)d_in[0];
    const int*   eidx = (const int*)d_in[1];
    const float* ew   = (const float*)d_in[2];
    const int*   et   = (const int*)d_in[3];
    const float* W1   = (const float*)d_in[4];
    const float* b1   = (const float*)d_in[5];
    const float* W2   = (const float*)d_in[6];
    const float* b2   = (const float*)d_in[7];
    const float* W3   = (const float*)d_in[8];
    const float* b3   = (const float*)d_in[9];
    float*       out  = (float*)d_out;

    void* p;
    float *xw1, *h1, *xw2, *h2, *xw3;
    cudaGetSymbolAddress(&p, g_xw1); xw1 = (float*)p;
    cudaGetSymbolAddress(&p, g_h1 ); h1  = (float*)p;
    cudaGetSymbolAddress(&p, g_xw2); xw2 = (float*)p;
    cudaGetSymbolAddress(&p, g_h2 ); h2  = (float*)p;
    cudaGetSymbolAddress(&p, g_xw3); xw3 = (float*)p;

    // ---- layer 1: xw1[r] = b_z @ W1[r]; h1 = bias1 + scatter ----
    rgemm<128, 128, 8, 8, 8, D0, D1, false>
        <<<dim3(N_NODES / 128, 1, N_REL), 256>>>(b_z, W1, xw1);
    init_bias<D1><<<(N_NODES * D1 + 255) / 256, 256>>>(h1, b1);
    edge_scatter<D1><<<N_EDGES / 8, 256>>>(xw1, eidx, ew, et, h1);

    // ---- layer 2: xw2[r] = relu(h1) @ W2[r]; h2 = bias2 + scatter ----
    rgemm<128, 64, 8, 8, 4, D1, D2, true>
        <<<dim3(N_NODES / 128, 1, N_REL), 256>>>(h1, W2, xw2);
    init_bias<D2><<<(N_NODES * D2 + 255) / 256, 256>>>(h2, b2);
    edge_scatter<D2><<<N_EDGES / 16, 256>>>(xw2, eidx, ew, et, h2);

    // ---- layer 3: xw3[r,n] = relu(h2[n]) . W3[r]; out = bias3 + scatter ----
    gemm3_kernel<<<(N_NODES + 255) / 256, 256>>>(h2, W3, xw3);
    init_out<<<(N_NODES + 255) / 256, 256>>>(out, b3);
    edge_scatter1<<<N_EDGES / 256, 256>>>(xw3, eidx, ew, et, out);
}

// round 6
// speedup vs baseline: 1.4862x; 1.4862x over previous
#include <cuda_runtime.h>
#include <cstdint>
#include <cstddef>

#define N_NODES 102400
#define N_EDGES 1638400
#define N_REL   8
#define D0      256
#define D1      128
#define D2      64

// ---------------- scratch (device globals; no allocation allowed) ----------
__device__ __align__(16) float g_xw1[(size_t)N_REL * N_NODES * D1]; // 419 MB
__device__ __align__(16) float g_h1 [(size_t)N_NODES * D1];         // 52 MB
__device__ __align__(16) float g_xw2[(size_t)N_REL * N_NODES * D2]; // 210 MB
__device__ __align__(16) float g_h2 [(size_t)N_NODES * D2];         // 26 MB
__device__ __align__(16) float g_xw3[(size_t)N_REL * N_NODES];      // 3.3 MB

__device__ __forceinline__ float to_tf32(float x) {
    float y;
    asm("cvt.rna.tf32.f32 %0, %1;" : "=f"(y) : "f"(x));
    return y;
}

__device__ __forceinline__ void mma_tf32(float* c, const uint32_t* a,
                                         uint32_t b0, uint32_t b1) {
    asm volatile(
        "mma.sync.aligned.m16n8k8.row.col.f32.tf32.tf32.f32 "
        "{%0,%1,%2,%3}, {%4,%5,%6,%7}, {%8,%9}, {%0,%1,%2,%3};"
        : "+f"(c[0]), "+f"(c[1]), "+f"(c[2]), "+f"(c[3])
        : "r"(a[0]), "r"(a[1]), "r"(a[2]), "r"(a[3]), "r"(b0), "r"(b1));
}

// ============== mma.sync tf32 batched per-relation GEMM ====================
// C[r] = (relu?)A @ B[r];  A:[N_NODES,Kdim] row-major, B[r]:[Kdim,BN] row-major
// blockIdx.x = relation (fast-varying -> L2 reuse of A tile across relations)
// blockIdx.y = M tile (BM=128). 256 threads = 8 warps as 4(M) x 2(N).
// tf32 m16n8k8 fragment layout (PTX ISA):
//   A: a0=(g,t) a1=(g+8,t) a2=(g,t+4) a3=(g+8,t+4)    g=lane/4, t=lane%4
//   B: b0=(n=g,k=t) b1=(n=g,k=t+4)
//   C: c0,c1=(g,2t),(g,2t+1); c2,c3=(g+8,2t),(g+8,2t+1)
template<int BN, int Kdim, bool RELU>
__global__ __launch_bounds__(256)
void rgemm_mma(const float* __restrict__ A, const float* __restrict__ B,
               float* __restrict__ C) {
    constexpr int BM = 128, BK = 32, PAD = 40;
    constexpr int WN = BN / 2;     // warp col span
    constexpr int NT = WN / 8;     // n8 tiles per warp

    __shared__ float As[BM][PAD];
    __shared__ float Bs[BN][PAD];

    const int r   = blockIdx.x;
    const int m0  = blockIdx.y * BM;
    const int tid = threadIdx.x;
    const int lane = tid & 31, wid = tid >> 5;
    const int mi = wid & 3, ni = wid >> 2;
    const int g = lane >> 2, t = lane & 3;

    const float* Ab = A + (size_t)m0 * Kdim;
    const float* Br = B + (size_t)r * Kdim * BN;
    float*       Cr = C + (size_t)r * N_NODES * BN + (size_t)m0 * BN;

    float acc[2][NT][4];
#pragma unroll
    for (int mt = 0; mt < 2; mt++)
#pragma unroll
        for (int nt = 0; nt < NT; nt++)
#pragma unroll
            for (int j = 0; j < 4; j++) acc[mt][nt][j] = 0.f;

    for (int c = 0; c < Kdim / BK; c++) {
        // ---- A tile 128x32 (row-major, relu+tf32 fused) ----
#pragma unroll
        for (int i = 0; i < (BM * BK / 4) / 256; i++) {
            int id  = i * 256 + tid;
            int row = id >> 3, c4 = (id & 7) * 4;
            float4 v = *(const float4*)&Ab[(size_t)row * Kdim + c * BK + c4];
            if (RELU) {
                v.x = fmaxf(v.x, 0.f); v.y = fmaxf(v.y, 0.f);
                v.z = fmaxf(v.z, 0.f); v.w = fmaxf(v.w, 0.f);
            }
            v.x = to_tf32(v.x); v.y = to_tf32(v.y);
            v.z = to_tf32(v.z); v.w = to_tf32(v.w);
            *(float4*)&As[row][c4] = v;
        }
        // ---- B tile 32xBN -> transposed Bs[n][k] (tf32 fused) ----
#pragma unroll
        for (int i = 0; i < (BK * BN / 4) / 256; i++) {
            int id = i * 256 + tid;
            int k = id & 31, n = (id >> 5) * 4;
            float4 v = *(const float4*)&Br[(size_t)(c * BK + k) * BN + n];
            Bs[n + 0][k] = to_tf32(v.x);
            Bs[n + 1][k] = to_tf32(v.y);
            Bs[n + 2][k] = to_tf32(v.z);
            Bs[n + 3][k] = to_tf32(v.w);
        }
        __syncthreads();

#pragma unroll
        for (int kk = 0; kk < 4; kk++) {
            const int kb = kk * 8 + t;       // k index for this thread
            uint32_t a[2][4];
#pragma unroll
            for (int mt = 0; mt < 2; mt++) {
                int row = mi * 32 + mt * 16 + g;
                a[mt][0] = __float_as_uint(As[row    ][kb    ]);
                a[mt][1] = __float_as_uint(As[row + 8][kb    ]);
                a[mt][2] = __float_as_uint(As[row    ][kb + 4]);
                a[mt][3] = __float_as_uint(As[row + 8][kb + 4]);
            }
#pragma unroll
            for (int nt = 0; nt < NT; nt++) {
                int n = ni * WN + nt * 8 + g;
                uint32_t b0 = __float_as_uint(Bs[n][kb    ]);
                uint32_t b1 = __float_as_uint(Bs[n][kb + 4]);
#pragma unroll
                for (int mt = 0; mt < 2; mt++)
                    mma_tf32(acc[mt][nt], a[mt], b0, b1);
            }
        }
        __syncthreads();
    }

    // ---- epilogue: float2 stores straight to gmem ----
#pragma unroll
    for (int mt = 0; mt < 2; mt++) {
        int row = mi * 32 + mt * 16 + g;
#pragma unroll
        for (int nt = 0; nt < NT; nt++) {
            int col = ni * WN + nt * 8 + t * 2;
            *(float2*)&Cr[(size_t)row * BN + col] =
                make_float2(acc[mt][nt][0], acc[mt][nt][1]);
            *(float2*)&Cr[(size_t)(row + 8) * BN + col] =
                make_float2(acc[mt][nt][2], acc[mt][nt][3]);
        }
    }
}

// ---------------- layer-3 transform: xw3[r,n] = relu(h2[n]) . W3[r] --------
__global__ void gemm3_kernel(const float* __restrict__ h2,
                             const float* __restrict__ W3,
                             float* __restrict__ xw3) {
    __shared__ float w[N_REL][D2];
    for (int i = threadIdx.x; i < N_REL * D2; i += blockDim.x)
        w[i / D2][i % D2] = W3[i];
    __syncthreads();

    int n = blockIdx.x * blockDim.x + threadIdx.x;
    if (n >= N_NODES) return;

    float acc[N_REL];
#pragma unroll
    for (int r = 0; r < N_REL; r++) acc[r] = 0.f;

    const float4* hp = (const float4*)&h2[(size_t)n * D2];
#pragma unroll
    for (int k4 = 0; k4 < D2 / 4; k4++) {
        float4 v = hp[k4];
        v.x = fmaxf(v.x, 0.f); v.y = fmaxf(v.y, 0.f);
        v.z = fmaxf(v.z, 0.f); v.w = fmaxf(v.w, 0.f);
#pragma unroll
        for (int r = 0; r < N_REL; r++) {
            acc[r] += v.x * w[r][k4 * 4 + 0];
            acc[r] += v.y * w[r][k4 * 4 + 1];
            acc[r] += v.z * w[r][k4 * 4 + 2];
            acc[r] += v.w * w[r][k4 * 4 + 3];
        }
    }
#pragma unroll
    for (int r = 0; r < N_REL; r++)
        xw3[(size_t)r * N_NODES + n] = acc[r];
}

// ---------------- bias init ------------------------------------------------
template<int D>
__global__ void init_bias(float* __restrict__ h, const float* __restrict__ bias) {
    size_t i = (size_t)blockIdx.x * blockDim.x + threadIdx.x;
    if (i < (size_t)N_NODES * D) h[i] = bias[i & (D - 1)];
}

__global__ void init_out(float* __restrict__ out, const float* __restrict__ b3) {
    int i = blockIdx.x * blockDim.x + threadIdx.x;
    if (i < N_NODES) out[i] = b3[0];
}

// ---------------- edge scatter: h[dst] += xw[etype, src] * ew --------------
template<int D>
__global__ void edge_scatter(const float* __restrict__ xw,
                             const int* __restrict__ eidx,
                             const float* __restrict__ ew,
                             const int* __restrict__ et,
                             float* __restrict__ h) {
    constexpr int LPE = D / 4;        // lanes per edge
    constexpr int EPW = 32 / LPE;     // edges per warp
    int warp = (blockIdx.x * blockDim.x + threadIdx.x) >> 5;
    int lane = threadIdx.x & 31;
    int e = warp * EPW + lane / LPE;
    if (e >= N_EDGES) return;
    int sub = (lane % LPE) * 4;

    int   src = eidx[e];
    int   dst = eidx[N_EDGES + e];
    int   t   = et[e];
    float w   = ew[e];

    float4 v = *(const float4*)&xw[((size_t)t * N_NODES + (size_t)src) * D + sub];
    float* o = &h[(size_t)dst * D + sub];
    atomicAdd(o + 0, v.x * w);
    atomicAdd(o + 1, v.y * w);
    atomicAdd(o + 2, v.z * w);
    atomicAdd(o + 3, v.w * w);
}

__global__ void edge_scatter1(const float* __restrict__ xw3,
                              const int* __restrict__ eidx,
                              const float* __restrict__ ew,
                              const int* __restrict__ et,
                              float* __restrict__ out) {
    int e = blockIdx.x * blockDim.x + threadIdx.x;
    if (e >= N_EDGES) return;
    int src = eidx[e];
    int dst = eidx[N_EDGES + e];
    int t   = et[e];
    atomicAdd(&out[dst], xw3[(size_t)t * N_NODES + (size_t)src] * ew[e]);
}

// ---------------- launcher --------------------------------------------------
extern "C" void kernel_launch(void* const* d_in, const int* in_sizes, int n_in,
                              void* d_out, int out_size) {
    const float* b_z  = (const float*)d_in[0];
    const int*   eidx = (const int*)d_in[1];
    const float* ew   = (const float*)d_in[2];
    const int*   et   = (const int*)d_in[3];
    const float* W1   = (const float*)d_in[4];
    const float* b1   = (const float*)d_in[5];
    const float* W2   = (const float*)d_in[6];
    const float* b2   = (const float*)d_in[7];
    const float* W3   = (const float*)d_in[8];
    const float* b3   = (const float*)d_in[9];
    float*       out  = (float*)d_out;

    void* p;
    float *xw1, *h1, *xw2, *h2, *xw3;
    cudaGetSymbolAddress(&p, g_xw1); xw1 = (float*)p;
    cudaGetSymbolAddress(&p, g_h1 ); h1  = (float*)p;
    cudaGetSymbolAddress(&p, g_xw2); xw2 = (float*)p;
    cudaGetSymbolAddress(&p, g_h2 ); h2  = (float*)p;
    cudaGetSymbolAddress(&p, g_xw3); xw3 = (float*)p;

    // ---- layer 1: xw1[r] = b_z @ W1[r]; h1 = bias1 + scatter ----
    rgemm_mma<128, 256, false>
        <<<dim3(N_REL, N_NODES / 128), 256>>>(b_z, W1, xw1);
    init_bias<D1><<<(N_NODES * D1 + 255) / 256, 256>>>(h1, b1);
    edge_scatter<D1><<<N_EDGES / 8, 256>>>(xw1, eidx, ew, et, h1);

    // ---- layer 2: xw2[r] = relu(h1) @ W2[r]; h2 = bias2 + scatter ----
    rgemm_mma<64, 128, true>
        <<<dim3(N_REL, N_NODES / 128), 256>>>(h1, W2, xw2);
    init_bias<D2><<<(N_NODES * D2 + 255) / 256, 256>>>(h2, b2);
    edge_scatter<D2><<<N_EDGES / 16, 256>>>(xw2, eidx, ew, et, h2);

    // ---- layer 3: xw3[r,n] = relu(h2[n]) . W3[r]; out = bias3 + scatter ----
    gemm3_kernel<<<(N_NODES + 255) / 256, 256>>>(h2, W3, xw3);
    init_out<<<(N_NODES + 255) / 256, 256>>>(out, b3);
    edge_scatter1<<<N_EDGES / 256, 256>>>(xw3, eidx, ew, et, out);
}

// round 7
// speedup vs baseline: 2.0516x; 1.3804x over previous
#include <cuda_runtime.h>
#include <cstdint>
#include <cstddef>

#define N_NODES 102400
#define N_EDGES 1638400
#define N_REL   8
#define D0      256
#define D1      128
#define D2      64

// ---------------- scratch (device globals; no allocation allowed) ----------
__device__ __align__(16) float g_xw1[(size_t)N_REL * N_NODES * D1]; // 419 MB
__device__ __align__(16) float g_h1 [(size_t)N_NODES * D1];         // 52 MB
__device__ __align__(16) float g_xw2[(size_t)N_REL * N_NODES * D2]; // 210 MB
__device__ __align__(16) float g_h2 [(size_t)N_NODES * D2];         // 26 MB
__device__ __align__(16) float g_xw3[(size_t)N_REL * N_NODES];      // 3.3 MB

__device__ __forceinline__ float to_tf32(float x) {
    float y;
    asm("cvt.rna.tf32.f32 %0, %1;" : "=f"(y) : "f"(x));
    return y;
}

__device__ __forceinline__ void mma_tf32(float* c, const uint32_t* a,
                                         uint32_t b0, uint32_t b1) {
    asm volatile(
        "mma.sync.aligned.m16n8k8.row.col.f32.tf32.tf32.f32 "
        "{%0,%1,%2,%3}, {%4,%5,%6,%7}, {%8,%9}, {%0,%1,%2,%3};"
        : "+f"(c[0]), "+f"(c[1]), "+f"(c[2]), "+f"(c[3])
        : "r"(a[0]), "r"(a[1]), "r"(a[2]), "r"(a[3]), "r"(b0), "r"(b1));
}

__device__ __forceinline__ void red_add_v4(float* addr, float a, float b,
                                           float c, float d) {
    asm volatile("red.global.add.v4.f32 [%0], {%1, %2, %3, %4};"
                 :: "l"(addr), "f"(a), "f"(b), "f"(c), "f"(d) : "memory");
}

// ============== mma.sync tf32 batched per-relation GEMM ====================
// C[r] = (relu?)A @ B[r];  A:[N_NODES,Kdim] row-major, B[r]:[Kdim,BN] row-major
// blockIdx.x = relation (fast-varying -> L2 reuse of A tile across relations)
// blockIdx.y = M tile (BM=128). 256 threads = 8 warps as 4(M) x 2(N).
// tf32 m16n8k8 fragment layout (PTX ISA):
//   A: a0=(g,t) a1=(g+8,t) a2=(g,t+4) a3=(g+8,t+4)    g=lane/4, t=lane%4
//   B: b0=(n=g,k=t) b1=(n=g,k=t+4)
//   C: c0,c1=(g,2t),(g,2t+1); c2,c3=(g+8,2t),(g+8,2t+1)
// PAD=36: row stride mod 32 banks = 4 -> lane bank = 4g + t, all 32 distinct
// -> conflict-free fragment LDS. 36 words = 144B keeps float4 alignment.
template<int BN, int Kdim, bool RELU>
__global__ __launch_bounds__(256)
void rgemm_mma(const float* __restrict__ A, const float* __restrict__ B,
               float* __restrict__ C) {
    constexpr int BM = 128, BK = 32, PAD = 36;
    constexpr int WN = BN / 2;     // warp col span
    constexpr int NT = WN / 8;     // n8 tiles per warp

    __shared__ float As[BM][PAD];
    __shared__ float Bs[BN][PAD];

    const int r   = blockIdx.x;
    const int m0  = blockIdx.y * BM;
    const int tid = threadIdx.x;
    const int lane = tid & 31, wid = tid >> 5;
    const int mi = wid & 3, ni = wid >> 2;
    const int g = lane >> 2, t = lane & 3;

    const float* Ab = A + (size_t)m0 * Kdim;
    const float* Br = B + (size_t)r * Kdim * BN;
    float*       Cr = C + (size_t)r * N_NODES * BN + (size_t)m0 * BN;

    float acc[2][NT][4];
#pragma unroll
    for (int mt = 0; mt < 2; mt++)
#pragma unroll
        for (int nt = 0; nt < NT; nt++)
#pragma unroll
            for (int j = 0; j < 4; j++) acc[mt][nt][j] = 0.f;

    for (int c = 0; c < Kdim / BK; c++) {
        // ---- A tile 128x32 (row-major, relu+tf32 fused) ----
#pragma unroll
        for (int i = 0; i < (BM * BK / 4) / 256; i++) {
            int id  = i * 256 + tid;
            int row = id >> 3, c4 = (id & 7) * 4;
            float4 v = *(const float4*)&Ab[(size_t)row * Kdim + c * BK + c4];
            if (RELU) {
                v.x = fmaxf(v.x, 0.f); v.y = fmaxf(v.y, 0.f);
                v.z = fmaxf(v.z, 0.f); v.w = fmaxf(v.w, 0.f);
            }
            v.x = to_tf32(v.x); v.y = to_tf32(v.y);
            v.z = to_tf32(v.z); v.w = to_tf32(v.w);
            *(float4*)&As[row][c4] = v;
        }
        // ---- B tile 32xBN -> transposed Bs[n][k] (tf32 fused) ----
#pragma unroll
        for (int i = 0; i < (BK * BN / 4) / 256; i++) {
            int id = i * 256 + tid;
            int k = id & 31, n = (id >> 5) * 4;
            float4 v = *(const float4*)&Br[(size_t)(c * BK + k) * BN + n];
            Bs[n + 0][k] = to_tf32(v.x);
            Bs[n + 1][k] = to_tf32(v.y);
            Bs[n + 2][k] = to_tf32(v.z);
            Bs[n + 3][k] = to_tf32(v.w);
        }
        __syncthreads();

#pragma unroll
        for (int kk = 0; kk < 4; kk++) {
            const int kb = kk * 8 + t;       // k index for this thread
            uint32_t a[2][4];
#pragma unroll
            for (int mt = 0; mt < 2; mt++) {
                int row = mi * 32 + mt * 16 + g;
                a[mt][0] = __float_as_uint(As[row    ][kb    ]);
                a[mt][1] = __float_as_uint(As[row + 8][kb    ]);
                a[mt][2] = __float_as_uint(As[row    ][kb + 4]);
                a[mt][3] = __float_as_uint(As[row + 8][kb + 4]);
            }
#pragma unroll
            for (int nt = 0; nt < NT; nt++) {
                int n = ni * WN + nt * 8 + g;
                uint32_t b0 = __float_as_uint(Bs[n][kb    ]);
                uint32_t b1 = __float_as_uint(Bs[n][kb + 4]);
#pragma unroll
                for (int mt = 0; mt < 2; mt++)
                    mma_tf32(acc[mt][nt], a[mt], b0, b1);
            }
        }
        __syncthreads();
    }

    // ---- epilogue: float2 stores straight to gmem ----
#pragma unroll
    for (int mt = 0; mt < 2; mt++) {
        int row = mi * 32 + mt * 16 + g;
#pragma unroll
        for (int nt = 0; nt < NT; nt++) {
            int col = ni * WN + nt * 8 + t * 2;
            *(float2*)&Cr[(size_t)row * BN + col] =
                make_float2(acc[mt][nt][0], acc[mt][nt][1]);
            *(float2*)&Cr[(size_t)(row + 8) * BN + col] =
                make_float2(acc[mt][nt][2], acc[mt][nt][3]);
        }
    }
}

// ---------------- layer-3 transform: xw3[r,n] = relu(h2[n]) . W3[r] --------
__global__ void gemm3_kernel(const float* __restrict__ h2,
                             const float* __restrict__ W3,
                             float* __restrict__ xw3) {
    __shared__ float w[N_REL][D2];
    for (int i = threadIdx.x; i < N_REL * D2; i += blockDim.x)
        w[i / D2][i % D2] = W3[i];
    __syncthreads();

    int n = blockIdx.x * blockDim.x + threadIdx.x;
    if (n >= N_NODES) return;

    float acc[N_REL];
#pragma unroll
    for (int r = 0; r < N_REL; r++) acc[r] = 0.f;

    const float4* hp = (const float4*)&h2[(size_t)n * D2];
#pragma unroll
    for (int k4 = 0; k4 < D2 / 4; k4++) {
        float4 v = hp[k4];
        v.x = fmaxf(v.x, 0.f); v.y = fmaxf(v.y, 0.f);
        v.z = fmaxf(v.z, 0.f); v.w = fmaxf(v.w, 0.f);
#pragma unroll
        for (int r = 0; r < N_REL; r++) {
            acc[r] += v.x * w[r][k4 * 4 + 0];
            acc[r] += v.y * w[r][k4 * 4 + 1];
            acc[r] += v.z * w[r][k4 * 4 + 2];
            acc[r] += v.w * w[r][k4 * 4 + 3];
        }
    }
#pragma unroll
    for (int r = 0; r < N_REL; r++)
        xw3[(size_t)r * N_NODES + n] = acc[r];
}

// ---------------- bias init ------------------------------------------------
template<int D>
__global__ void init_bias(float* __restrict__ h, const float* __restrict__ bias) {
    size_t i = (size_t)blockIdx.x * blockDim.x + threadIdx.x;
    if (i < (size_t)N_NODES * D) h[i] = bias[i & (D - 1)];
}

__global__ void init_out(float* __restrict__ out, const float* __restrict__ b3) {
    int i = blockIdx.x * blockDim.x + threadIdx.x;
    if (i < N_NODES) out[i] = b3[0];
}

// ---------------- edge scatter: h[dst] += xw[etype, src] * ew --------------
// One (sub-)warp group of D/4 lanes per edge: coalesced float4 gather from the
// xw row, one red.global.add.v4.f32 per lane into the h row (4x fewer LTS
// atomic ops than scalar atomicAdd).
template<int D>
__global__ void edge_scatter(const float* __restrict__ xw,
                             const int* __restrict__ eidx,
                             const float* __restrict__ ew,
                             const int* __restrict__ et,
                             float* __restrict__ h) {
    constexpr int LPE = D / 4;        // lanes per edge
    constexpr int EPW = 32 / LPE;     // edges per warp
    int warp = (blockIdx.x * blockDim.x + threadIdx.x) >> 5;
    int lane = threadIdx.x & 31;
    int e = warp * EPW + lane / LPE;
    if (e >= N_EDGES) return;
    int sub = (lane % LPE) * 4;

    int   src = eidx[e];
    int   dst = eidx[N_EDGES + e];
    int   t   = et[e];
    float w   = ew[e];

    float4 v = *(const float4*)&xw[((size_t)t * N_NODES + (size_t)src) * D + sub];
    float* o = &h[(size_t)dst * D + sub];
    red_add_v4(o, v.x * w, v.y * w, v.z * w, v.w * w);
}

__global__ void edge_scatter1(const float* __restrict__ xw3,
                              const int* __restrict__ eidx,
                              const float* __restrict__ ew,
                              const int* __restrict__ et,
                              float* __restrict__ out) {
    int e = blockIdx.x * blockDim.x + threadIdx.x;
    if (e >= N_EDGES) return;
    int src = eidx[e];
    int dst = eidx[N_EDGES + e];
    int t   = et[e];
    atomicAdd(&out[dst], xw3[(size_t)t * N_NODES + (size_t)src] * ew[e]);
}

// ---------------- launcher --------------------------------------------------
extern "C" void kernel_launch(void* const* d_in, const int* in_sizes, int n_in,
                              void* d_out, int out_size) {
    const float* b_z  = (const float*)d_in[0];
    const int*   eidx = (const int*)d_in[1];
    const float* ew   = (const float*)d_in[2];
    const int*   et   = (const int*)d_in[3];
    const float* W1   = (const float*)d_in[4];
    const float* b1   = (const float*)d_in[5];
    const float* W2   = (const float*)d_in[6];
    const float* b2   = (const float*)d_in[7];
    const float* W3   = (const float*)d_in[8];
    const float* b3   = (const float*)d_in[9];
    float*       out  = (float*)d_out;

    void* p;
    float *xw1, *h1, *xw2, *h2, *xw3;
    cudaGetSymbolAddress(&p, g_xw1); xw1 = (float*)p;
    cudaGetSymbolAddress(&p, g_h1 ); h1  = (float*)p;
    cudaGetSymbolAddress(&p, g_xw2); xw2 = (float*)p;
    cudaGetSymbolAddress(&p, g_h2 ); h2  = (float*)p;
    cudaGetSymbolAddress(&p, g_xw3); xw3 = (float*)p;

    // ---- layer 1: xw1[r] = b_z @ W1[r]; h1 = bias1 + scatter ----
    rgemm_mma<128, 256, false>
        <<<dim3(N_REL, N_NODES / 128), 256>>>(b_z, W1, xw1);
    init_bias<D1><<<(N_NODES * D1 + 255) / 256, 256>>>(h1, b1);
    edge_scatter<D1><<<N_EDGES / 8, 256>>>(xw1, eidx, ew, et, h1);

    // ---- layer 2: xw2[r] = relu(h1) @ W2[r]; h2 = bias2 + scatter ----
    rgemm_mma<64, 128, true>
        <<<dim3(N_REL, N_NODES / 128), 256>>>(h1, W2, xw2);
    init_bias<D2><<<(N_NODES * D2 + 255) / 256, 256>>>(h2, b2);
    edge_scatter<D2><<<N_EDGES / 16, 256>>>(xw2, eidx, ew, et, h2);

    // ---- layer 3: xw3[r,n] = relu(h2[n]) . W3[r]; out = bias3 + scatter ----
    gemm3_kernel<<<(N_NODES + 255) / 256, 256>>>(h2, W3, xw3);
    init_out<<<(N_NODES + 255) / 256, 256>>>(out, b3);
    edge_scatter1<<<N_EDGES / 256, 256>>>(xw3, eidx, ew, et, out);
}

// round 8
// speedup vs baseline: 2.1527x; 1.0493x over previous
#include <cuda_runtime.h>
#include <cstdint>
#include <cstddef>

#define N_NODES 102400
#define N_EDGES 1638400
#define N_REL   8
#define D0      256
#define D1      128
#define D2      64

// ---------------- scratch (device globals; no allocation allowed) ----------
__device__ __align__(16) float g_xw1[(size_t)N_REL * N_NODES * D1]; // 419 MB
__device__ __align__(16) float g_h1 [(size_t)N_NODES * D1];         // 52 MB
__device__ __align__(16) float g_xw2[(size_t)N_REL * N_NODES * D2]; // 210 MB
__device__ __align__(16) float g_h2 [(size_t)N_NODES * D2];         // 26 MB
__device__ __align__(16) float g_xw3[(size_t)N_REL * N_NODES];      // 3.3 MB

__device__ __forceinline__ float to_tf32(float x) {
    float y;
    asm("cvt.rna.tf32.f32 %0, %1;" : "=f"(y) : "f"(x));
    return y;
}

__device__ __forceinline__ void mma_tf32(float* c, const uint32_t* a,
                                         uint32_t b0, uint32_t b1) {
    asm volatile(
        "mma.sync.aligned.m16n8k8.row.col.f32.tf32.tf32.f32 "
        "{%0,%1,%2,%3}, {%4,%5,%6,%7}, {%8,%9}, {%0,%1,%2,%3};"
        : "+f"(c[0]), "+f"(c[1]), "+f"(c[2]), "+f"(c[3])
        : "r"(a[0]), "r"(a[1]), "r"(a[2]), "r"(a[3]), "r"(b0), "r"(b1));
}

__device__ __forceinline__ void ldsm_x4(uint32_t* r, uint32_t saddr) {
    asm volatile(
        "ldmatrix.sync.aligned.m8n8.x4.shared.b16 {%0,%1,%2,%3}, [%4];"
        : "=r"(r[0]), "=r"(r[1]), "=r"(r[2]), "=r"(r[3]) : "r"(saddr));
}

__device__ __forceinline__ uint32_t smem_u32(const void* p) {
    return (uint32_t)__cvta_generic_to_shared(p);
}

__device__ __forceinline__ void red_add_v4(float* addr, float a, float b,
                                           float c, float d) {
    asm volatile("red.global.add.v4.f32 [%0], {%1, %2, %3, %4};"
                 :: "l"(addr), "f"(a), "f"(b), "f"(c), "f"(d) : "memory");
}

// ============== mma.sync tf32 batched per-relation GEMM ====================
// C[r] = (relu?)A @ B[r];  A:[N_NODES,Kdim] row-major, B[r]:[Kdim,BN] row-major
// blockIdx.x = relation (fast-varying -> L2 reuse of A tile across relations)
// blockIdx.y = M tile (BM=128). 256 threads = 8 warps as 4(M) x 2(N).
// Fragments loaded via ldmatrix.x4: one 8x8 tf32 tile = m8n16 b16 = 2 LDSM
// matrices; thread l gets row l/4, bytes 4*(l%4) == tf32 (g,t) mapping.
// PAD=36: 144B row stride -> 8 LDSM row addresses at banks 4g, 4 banks each
// -> all 32 banks exactly once, conflict-free.
template<int BN, int Kdim, bool RELU>
__global__ __launch_bounds__(256)
void rgemm_mma(const float* __restrict__ A, const float* __restrict__ B,
               float* __restrict__ C) {
    constexpr int BM = 128, BK = 32, PAD = 36;
    constexpr int WN = BN / 2;     // warp col span
    constexpr int NT = WN / 8;     // n8 tiles per warp
    constexpr int NP = NT / 2;     // nt pairs

    __shared__ float As[BM][PAD];
    __shared__ float Bs[BN][PAD];

    const int r   = blockIdx.x;
    const int m0  = blockIdx.y * BM;
    const int tid = threadIdx.x;
    const int lane = tid & 31, wid = tid >> 5;
    const int mi = wid & 3, ni = wid >> 2;
    const int g = lane >> 2, t = lane & 3;

    const float* Ab = A + (size_t)m0 * Kdim;
    const float* Br = B + (size_t)r * Kdim * BN;
    float*       Cr = C + (size_t)r * N_NODES * BN + (size_t)m0 * BN;

    // ---- ldmatrix per-thread source addresses (row part; kk adds 32B) ----
    const int j8 = lane >> 3, i8 = lane & 7;
    // A matrices: m0=rows[0:8) kleft, m1=rows[8:16) kleft, m2=[0:8) kright, m3=[8:16) kright
    uint32_t aAddr[2];
#pragma unroll
    for (int mt = 0; mt < 2; mt++) {
        int row = mi * 32 + mt * 16 + (j8 & 1) * 8 + i8;
        aAddr[mt] = smem_u32(&As[row][0]) + (j8 >> 1) * 16;
    }
    // B matrices: m0=nt rows kleft, m1=nt rows kright, m2=nt+1 kleft, m3=nt+1 kright
    uint32_t bAddr[NP];
#pragma unroll
    for (int p = 0; p < NP; p++) {
        int nrow = ni * WN + p * 16 + (j8 >> 1) * 8 + i8;
        bAddr[p] = smem_u32(&Bs[nrow][0]) + (j8 & 1) * 16;
    }

    float acc[2][NT][4];
#pragma unroll
    for (int mt = 0; mt < 2; mt++)
#pragma unroll
        for (int nt = 0; nt < NT; nt++)
#pragma unroll
            for (int q = 0; q < 4; q++) acc[mt][nt][q] = 0.f;

    for (int c = 0; c < Kdim / BK; c++) {
        // ---- A tile 128x32 (row-major, relu+tf32 fused) ----
#pragma unroll
        for (int i = 0; i < (BM * BK / 4) / 256; i++) {
            int id  = i * 256 + tid;
            int row = id >> 3, c4 = (id & 7) * 4;
            float4 v = *(const float4*)&Ab[(size_t)row * Kdim + c * BK + c4];
            if (RELU) {
                v.x = fmaxf(v.x, 0.f); v.y = fmaxf(v.y, 0.f);
                v.z = fmaxf(v.z, 0.f); v.w = fmaxf(v.w, 0.f);
            }
            v.x = to_tf32(v.x); v.y = to_tf32(v.y);
            v.z = to_tf32(v.z); v.w = to_tf32(v.w);
            *(float4*)&As[row][c4] = v;
        }
        // ---- B tile 32xBN -> transposed Bs[n][k] (tf32 fused) ----
#pragma unroll
        for (int i = 0; i < (BK * BN / 4) / 256; i++) {
            int id = i * 256 + tid;
            int k = id & 31, n = (id >> 5) * 4;
            float4 v = *(const float4*)&Br[(size_t)(c * BK + k) * BN + n];
            Bs[n + 0][k] = to_tf32(v.x);
            Bs[n + 1][k] = to_tf32(v.y);
            Bs[n + 2][k] = to_tf32(v.z);
            Bs[n + 3][k] = to_tf32(v.w);
        }
        __syncthreads();

#pragma unroll
        for (int kk = 0; kk < 4; kk++) {
            uint32_t a[2][4];
            ldsm_x4(a[0], aAddr[0] + kk * 32);
            ldsm_x4(a[1], aAddr[1] + kk * 32);
#pragma unroll
            for (int p = 0; p < NP; p++) {
                uint32_t b[4];
                ldsm_x4(b, bAddr[p] + kk * 32);
#pragma unroll
                for (int mt = 0; mt < 2; mt++) {
                    mma_tf32(acc[mt][2 * p],     a[mt], b[0], b[1]);
                    mma_tf32(acc[mt][2 * p + 1], a[mt], b[2], b[3]);
                }
            }
        }
        __syncthreads();
    }

    // ---- epilogue: float2 stores straight to gmem ----
#pragma unroll
    for (int mt = 0; mt < 2; mt++) {
        int row = mi * 32 + mt * 16 + g;
#pragma unroll
        for (int nt = 0; nt < NT; nt++) {
            int col = ni * WN + nt * 8 + t * 2;
            *(float2*)&Cr[(size_t)row * BN + col] =
                make_float2(acc[mt][nt][0], acc[mt][nt][1]);
            *(float2*)&Cr[(size_t)(row + 8) * BN + col] =
                make_float2(acc[mt][nt][2], acc[mt][nt][3]);
        }
    }
}

// ---------------- layer-3 transform: xw3[r,n] = relu(h2[n]) . W3[r] --------
__global__ void gemm3_kernel(const float* __restrict__ h2,
                             const float* __restrict__ W3,
                             float* __restrict__ xw3) {
    __shared__ float w[N_REL][D2];
    for (int i = threadIdx.x; i < N_REL * D2; i += blockDim.x)
        w[i / D2][i % D2] = W3[i];
    __syncthreads();

    int n = blockIdx.x * blockDim.x + threadIdx.x;
    if (n >= N_NODES) return;

    float acc[N_REL];
#pragma unroll
    for (int r = 0; r < N_REL; r++) acc[r] = 0.f;

    const float4* hp = (const float4*)&h2[(size_t)n * D2];
#pragma unroll
    for (int k4 = 0; k4 < D2 / 4; k4++) {
        float4 v = hp[k4];
        v.x = fmaxf(v.x, 0.f); v.y = fmaxf(v.y, 0.f);
        v.z = fmaxf(v.z, 0.f); v.w = fmaxf(v.w, 0.f);
#pragma unroll
        for (int r = 0; r < N_REL; r++) {
            acc[r] += v.x * w[r][k4 * 4 + 0];
            acc[r] += v.y * w[r][k4 * 4 + 1];
            acc[r] += v.z * w[r][k4 * 4 + 2];
            acc[r] += v.w * w[r][k4 * 4 + 3];
        }
    }
#pragma unroll
    for (int r = 0; r < N_REL; r++)
        xw3[(size_t)r * N_NODES + n] = acc[r];
}

// ---------------- bias init ------------------------------------------------
template<int D>
__global__ void init_bias(float* __restrict__ h, const float* __restrict__ bias) {
    size_t i = (size_t)blockIdx.x * blockDim.x + threadIdx.x;
    if (i < (size_t)N_NODES * D) h[i] = bias[i & (D - 1)];
}

__global__ void init_out(float* __restrict__ out, const float* __restrict__ b3) {
    int i = blockIdx.x * blockDim.x + threadIdx.x;
    if (i < N_NODES) out[i] = b3[0];
}

// ---------------- edge scatter: h[dst] += xw[etype, src] * ew --------------
template<int D>
__global__ void edge_scatter(const float* __restrict__ xw,
                             const int* __restrict__ eidx,
                             const float* __restrict__ ew,
                             const int* __restrict__ et,
                             float* __restrict__ h) {
    constexpr int LPE = D / 4;        // lanes per edge
    constexpr int EPW = 32 / LPE;     // edges per warp
    int warp = (blockIdx.x * blockDim.x + threadIdx.x) >> 5;
    int lane = threadIdx.x & 31;
    int e = warp * EPW + lane / LPE;
    if (e >= N_EDGES) return;
    int sub = (lane % LPE) * 4;

    int   src = eidx[e];
    int   dst = eidx[N_EDGES + e];
    int   t   = et[e];
    float w   = ew[e];

    float4 v = *(const float4*)&xw[((size_t)t * N_NODES + (size_t)src) * D + sub];
    float* o = &h[(size_t)dst * D + sub];
    red_add_v4(o, v.x * w, v.y * w, v.z * w, v.w * w);
}

__global__ void edge_scatter1(const float* __restrict__ xw3,
                              const int* __restrict__ eidx,
                              const float* __restrict__ ew,
                              const int* __restrict__ et,
                              float* __restrict__ out) {
    int e = blockIdx.x * blockDim.x + threadIdx.x;
    if (e >= N_EDGES) return;
    int src = eidx[e];
    int dst = eidx[N_EDGES + e];
    int t   = et[e];
    atomicAdd(&out[dst], xw3[(size_t)t * N_NODES + (size_t)src] * ew[e]);
}

// ---------------- launcher --------------------------------------------------
extern "C" void kernel_launch(void* const* d_in, const int* in_sizes, int n_in,
                              void* d_out, int out_size) {
    const float* b_z  = (const float*)d_in[0];
    const int*   eidx = (const int*)d_in[1];
    const float* ew   = (const float*)d_in[2];
    const int*   et   = (const int*)d_in[3];
    const float* W1   = (const float*)d_in[4];
    const float* b1   = (const float*)d_in[5];
    const float* W2   = (const float*)d_in[6];
    const float* b2   = (const float*)d_in[7];
    const float* W3   = (const float*)d_in[8];
    const float* b3   = (const float*)d_in[9];
    float*       out  = (float*)d_out;

    void* p;
    float *xw1, *h1, *xw2, *h2, *xw3;
    cudaGetSymbolAddress(&p, g_xw1); xw1 = (float*)p;
    cudaGetSymbolAddress(&p, g_h1 ); h1  = (float*)p;
    cudaGetSymbolAddress(&p, g_xw2); xw2 = (float*)p;
    cudaGetSymbolAddress(&p, g_h2 ); h2  = (float*)p;
    cudaGetSymbolAddress(&p, g_xw3); xw3 = (float*)p;

    // ---- layer 1: xw1[r] = b_z @ W1[r]; h1 = bias1 + scatter ----
    rgemm_mma<128, 256, false>
        <<<dim3(N_REL, N_NODES / 128), 256>>>(b_z, W1, xw1);
    init_bias<D1><<<(N_NODES * D1 + 255) / 256, 256>>>(h1, b1);
    edge_scatter<D1><<<N_EDGES / 8, 256>>>(xw1, eidx, ew, et, h1);

    // ---- layer 2: xw2[r] = relu(h1) @ W2[r]; h2 = bias2 + scatter ----
    rgemm_mma<64, 128, true>
        <<<dim3(N_REL, N_NODES / 128), 256>>>(h1, W2, xw2);
    init_bias<D2><<<(N_NODES * D2 + 255) / 256, 256>>>(h2, b2);
    edge_scatter<D2><<<N_EDGES / 16, 256>>>(xw2, eidx, ew, et, h2);

    // ---- layer 3: xw3[r,n] = relu(h2[n]) . W3[r]; out = bias3 + scatter ----
    gemm3_kernel<<<(N_NODES + 255) / 256, 256>>>(h2, W3, xw3);
    init_out<<<(N_NODES + 255) / 256, 256>>>(out, b3);
    edge_scatter1<<<N_EDGES / 256, 256>>>(xw3, eidx, ew, et, out);
}

// round 9
// speedup vs baseline: 2.5162x; 1.1689x over previous
#include <cuda_runtime.h>
#include <cstdint>
#include <cstddef>

#define N_NODES 102400
#define N_EDGES 1638400
#define N_REL   8
#define D0      256
#define D1      128
#define D2      64

// ---------------- scratch (device globals; no allocation allowed) ----------
__device__ __align__(16) float g_xw1[(size_t)N_REL * N_NODES * D1]; // 419 MB
__device__ __align__(16) float g_h1 [(size_t)N_NODES * D1];         // 52 MB
__device__ __align__(16) float g_xw2[(size_t)N_REL * N_NODES * D2]; // 210 MB
__device__ __align__(16) float g_h2 [(size_t)N_NODES * D2];         // 26 MB
__device__ __align__(16) float g_xw3[(size_t)N_REL * N_NODES];      // 3.3 MB
__device__ __align__(16) float g_a1 [(size_t)N_NODES * D0];         // 105 MB (tf32 b_z)
__device__ __align__(16) float g_a2 [(size_t)N_NODES * D1];         // 52 MB (tf32 relu h1)
__device__ __align__(16) float g_w1t[(size_t)N_REL * D1 * D0];      // 1 MB  [r][n][k]
__device__ __align__(16) float g_w2t[(size_t)N_REL * D2 * D1];      // 0.25 MB

__device__ __forceinline__ float to_tf32(float x) {
    float y;
    asm("cvt.rna.tf32.f32 %0, %1;" : "=f"(y) : "f"(x));
    return y;
}

__device__ __forceinline__ void mma_tf32(float* c, const uint32_t* a,
                                         uint32_t b0, uint32_t b1) {
    asm volatile(
        "mma.sync.aligned.m16n8k8.row.col.f32.tf32.tf32.f32 "
        "{%0,%1,%2,%3}, {%4,%5,%6,%7}, {%8,%9}, {%0,%1,%2,%3};"
        : "+f"(c[0]), "+f"(c[1]), "+f"(c[2]), "+f"(c[3])
        : "r"(a[0]), "r"(a[1]), "r"(a[2]), "r"(a[3]), "r"(b0), "r"(b1));
}

__device__ __forceinline__ void ldsm_x4(uint32_t* r, uint32_t saddr) {
    asm volatile(
        "ldmatrix.sync.aligned.m8n8.x4.shared.b16 {%0,%1,%2,%3}, [%4];"
        : "=r"(r[0]), "=r"(r[1]), "=r"(r[2]), "=r"(r[3]) : "r"(saddr));
}

__device__ __forceinline__ uint32_t smem_u32(const void* p) {
    return (uint32_t)__cvta_generic_to_shared(p);
}

__device__ __forceinline__ void red_add_v4(float* addr, float a, float b,
                                           float c, float d) {
    asm volatile("red.global.add.v4.f32 [%0], {%1, %2, %3, %4};"
                 :: "l"(addr), "f"(a), "f"(b), "f"(c), "f"(d) : "memory");
}

#define CP_ASYNC16(dst, src) \
    asm volatile("cp.async.cg.shared.global [%0], [%1], 16;" \
                 :: "r"(dst), "l"(src) : "memory")
#define CP_COMMIT() asm volatile("cp.async.commit_group;" ::: "memory")
#define CP_WAIT(n)  asm volatile("cp.async.wait_group %0;" :: "n"(n) : "memory")

// ============== cp.async double-buffered tf32 batched GEMM =================
// C[r] = A @ Bt[r]^T;  A:[N_NODES,Kdim] (pre-rounded tf32), Bt:[R][BN][Kdim]
// (pre-rounded + pre-transposed). blockIdx.x = relation, blockIdx.y = M tile.
// 256 threads = 8 warps as 4(M) x 2(N). 2-stage cp.async pipeline.
// PAD=36 (144B rows): 16B-aligned for cp.async, conflict-free for ldmatrix.
template<int BN, int Kdim>
__global__ __launch_bounds__(256)
void rgemm_cp(const float* __restrict__ A, const float* __restrict__ Bt,
              float* __restrict__ C) {
    constexpr int BM = 128, BK = 32, PAD = 36;
    constexpr int NCH = Kdim / BK;
    constexpr int WN = BN / 2, NT = WN / 8, NP = NT / 2;
    constexpr int ASTR = BM * PAD;          // floats per A stage
    constexpr int BSTR = BN * PAD;

    extern __shared__ __align__(16) float sm[];
    float* Asm = sm;                        // [2][BM][PAD]
    float* Bsm = sm + 2 * ASTR;             // [2][BN][PAD]

    const int r   = blockIdx.x;
    const int m0  = blockIdx.y * BM;
    const int tid = threadIdx.x;
    const int lane = tid & 31, wid = tid >> 5;
    const int mi = wid & 3, ni = wid >> 2;
    const int g = lane >> 2, t = lane & 3;

    const float* Ab = A + (size_t)m0 * Kdim;
    const float* Bb = Bt + (size_t)r * BN * Kdim;
    float*       Cr = C + (size_t)r * N_NODES * BN + (size_t)m0 * BN;

    // ---- ldmatrix per-thread addresses (stage 0; add stage/kk offsets) ----
    const int j8 = lane >> 3, i8 = lane & 7;
    uint32_t aAddr[2];
#pragma unroll
    for (int mt = 0; mt < 2; mt++) {
        int row = mi * 32 + mt * 16 + (j8 & 1) * 8 + i8;
        aAddr[mt] = smem_u32(&Asm[row * PAD]) + (j8 >> 1) * 16;
    }
    uint32_t bAddr[NP];
#pragma unroll
    for (int p = 0; p < NP; p++) {
        int nrow = ni * WN + p * 16 + (j8 >> 1) * 8 + i8;
        bAddr[p] = smem_u32(&Bsm[nrow * PAD]) + (j8 & 1) * 16;
    }

    // ---- tile loader: raw 16B cp.async copies (data pre-rounded) ----
    auto load_stage = [&](int c, int s) {
        float* Ad = Asm + s * ASTR;
#pragma unroll
        for (int i = 0; i < 4; i++) {
            int idx = i * 256 + tid;
            int row = idx >> 3, ch = (idx & 7) * 4;
            CP_ASYNC16(smem_u32(Ad + row * PAD + ch),
                       Ab + (size_t)row * Kdim + c * BK + ch);
        }
        float* Bd = Bsm + s * BSTR;
#pragma unroll
        for (int i = 0; i < BN / 32; i++) {
            int idx = i * 256 + tid;
            int row = idx >> 3, ch = (idx & 7) * 4;
            CP_ASYNC16(smem_u32(Bd + row * PAD + ch),
                       Bb + (size_t)row * Kdim + c * BK + ch);
        }
        CP_COMMIT();
    };

    float acc[2][NT][4];
#pragma unroll
    for (int mt = 0; mt < 2; mt++)
#pragma unroll
        for (int nt = 0; nt < NT; nt++)
#pragma unroll
            for (int q = 0; q < 4; q++) acc[mt][nt][q] = 0.f;

    load_stage(0, 0);
    load_stage(1, 1);

    for (int c = 0; c < NCH; c++) {
        const int s = c & 1;
        if (c + 1 < NCH) { CP_WAIT(1); } else { CP_WAIT(0); }
        __syncthreads();

        const uint32_t ao = s * ASTR * 4, bo = s * BSTR * 4;
#pragma unroll
        for (int kk = 0; kk < 4; kk++) {
            uint32_t a[2][4];
            ldsm_x4(a[0], aAddr[0] + ao + kk * 32);
            ldsm_x4(a[1], aAddr[1] + ao + kk * 32);
#pragma unroll
            for (int p = 0; p < NP; p++) {
                uint32_t b[4];
                ldsm_x4(b, bAddr[p] + bo + kk * 32);
#pragma unroll
                for (int mt = 0; mt < 2; mt++) {
                    mma_tf32(acc[mt][2 * p],     a[mt], b[0], b[1]);
                    mma_tf32(acc[mt][2 * p + 1], a[mt], b[2], b[3]);
                }
            }
        }
        __syncthreads();
        if (c + 2 < NCH) load_stage(c + 2, s);
    }

    // ---- epilogue: float2 stores straight to gmem ----
#pragma unroll
    for (int mt = 0; mt < 2; mt++) {
        int row = mi * 32 + mt * 16 + g;
#pragma unroll
        for (int nt = 0; nt < NT; nt++) {
            int col = ni * WN + nt * 8 + t * 2;
            *(float2*)&Cr[(size_t)row * BN + col] =
                make_float2(acc[mt][nt][0], acc[mt][nt][1]);
            *(float2*)&Cr[(size_t)(row + 8) * BN + col] =
                make_float2(acc[mt][nt][2], acc[mt][nt][3]);
        }
    }
}

// ---------------- pre-pass: tf32 rounding (+optional relu) -----------------
template<bool RELU>
__global__ void round_tf32(const float* __restrict__ src,
                           float* __restrict__ dst, size_t n4) {
    size_t i = (size_t)blockIdx.x * blockDim.x + threadIdx.x;
    if (i >= n4) return;
    float4 v = *(const float4*)(src + i * 4);
    if (RELU) {
        v.x = fmaxf(v.x, 0.f); v.y = fmaxf(v.y, 0.f);
        v.z = fmaxf(v.z, 0.f); v.w = fmaxf(v.w, 0.f);
    }
    v.x = to_tf32(v.x); v.y = to_tf32(v.y);
    v.z = to_tf32(v.z); v.w = to_tf32(v.w);
    *(float4*)(dst + i * 4) = v;
}

// W[r][k][n] -> Wt[r][n][k], tf32-rounded
template<int K, int N>
__global__ void transpose_w(const float* __restrict__ W,
                            float* __restrict__ Wt) {
    int r = blockIdx.y;
    int idx = blockIdx.x * 256 + threadIdx.x;
    if (idx >= K * N) return;
    int k = idx / N, n = idx % N;
    Wt[((size_t)r * N + n) * K + k] = to_tf32(W[((size_t)r * K + k) * N + n]);
}

// ---------------- layer-3 transform: xw3[r,n] = relu(h2[n]) . W3[r] --------
__global__ void gemm3_kernel(const float* __restrict__ h2,
                             const float* __restrict__ W3,
                             float* __restrict__ xw3) {
    __shared__ float w[N_REL][D2];
    for (int i = threadIdx.x; i < N_REL * D2; i += blockDim.x)
        w[i / D2][i % D2] = W3[i];
    __syncthreads();

    int n = blockIdx.x * blockDim.x + threadIdx.x;
    if (n >= N_NODES) return;

    float acc[N_REL];
#pragma unroll
    for (int r = 0; r < N_REL; r++) acc[r] = 0.f;

    const float4* hp = (const float4*)&h2[(size_t)n * D2];
#pragma unroll
    for (int k4 = 0; k4 < D2 / 4; k4++) {
        float4 v = hp[k4];
        v.x = fmaxf(v.x, 0.f); v.y = fmaxf(v.y, 0.f);
        v.z = fmaxf(v.z, 0.f); v.w = fmaxf(v.w, 0.f);
#pragma unroll
        for (int r = 0; r < N_REL; r++) {
            acc[r] += v.x * w[r][k4 * 4 + 0];
            acc[r] += v.y * w[r][k4 * 4 + 1];
            acc[r] += v.z * w[r][k4 * 4 + 2];
            acc[r] += v.w * w[r][k4 * 4 + 3];
        }
    }
#pragma unroll
    for (int r = 0; r < N_REL; r++)
        xw3[(size_t)r * N_NODES + n] = acc[r];
}

// ---------------- bias init ------------------------------------------------
template<int D>
__global__ void init_bias(float* __restrict__ h, const float* __restrict__ bias) {
    size_t i = (size_t)blockIdx.x * blockDim.x + threadIdx.x;
    if (i < (size_t)N_NODES * D) h[i] = bias[i & (D - 1)];
}

__global__ void init_out(float* __restrict__ out, const float* __restrict__ b3) {
    int i = blockIdx.x * blockDim.x + threadIdx.x;
    if (i < N_NODES) out[i] = b3[0];
}

// ---------------- edge scatter: h[dst] += xw[etype, src] * ew --------------
template<int D>
__global__ void edge_scatter(const float* __restrict__ xw,
                             const int* __restrict__ eidx,
                             const float* __restrict__ ew,
                             const int* __restrict__ et,
                             float* __restrict__ h) {
    constexpr int LPE = D / 4;        // lanes per edge
    constexpr int EPW = 32 / LPE;     // edges per warp
    int warp = (blockIdx.x * blockDim.x + threadIdx.x) >> 5;
    int lane = threadIdx.x & 31;
    int e = warp * EPW + lane / LPE;
    if (e >= N_EDGES) return;
    int sub = (lane % LPE) * 4;

    int   src = eidx[e];
    int   dst = eidx[N_EDGES + e];
    int   t   = et[e];
    float w   = ew[e];

    float4 v = *(const float4*)&xw[((size_t)t * N_NODES + (size_t)src) * D + sub];
    float* o = &h[(size_t)dst * D + sub];
    red_add_v4(o, v.x * w, v.y * w, v.z * w, v.w * w);
}

__global__ void edge_scatter1(const float* __restrict__ xw3,
                              const int* __restrict__ eidx,
                              const float* __restrict__ ew,
                              const int* __restrict__ et,
                              float* __restrict__ out) {
    int e = blockIdx.x * blockDim.x + threadIdx.x;
    if (e >= N_EDGES) return;
    int src = eidx[e];
    int dst = eidx[N_EDGES + e];
    int t   = et[e];
    atomicAdd(&out[dst], xw3[(size_t)t * N_NODES + (size_t)src] * ew[e]);
}

// ---------------- launcher --------------------------------------------------
extern "C" void kernel_launch(void* const* d_in, const int* in_sizes, int n_in,
                              void* d_out, int out_size) {
    const float* b_z  = (const float*)d_in[0];
    const int*   eidx = (const int*)d_in[1];
    const float* ew   = (const float*)d_in[2];
    const int*   et   = (const int*)d_in[3];
    const float* W1   = (const float*)d_in[4];
    const float* b1   = (const float*)d_in[5];
    const float* W2   = (const float*)d_in[6];
    const float* b2   = (const float*)d_in[7];
    const float* W3   = (const float*)d_in[8];
    const float* b3   = (const float*)d_in[9];
    float*       out  = (float*)d_out;

    void* p;
    float *xw1, *h1, *xw2, *h2, *xw3, *a1, *a2, *w1t, *w2t;
    cudaGetSymbolAddress(&p, g_xw1); xw1 = (float*)p;
    cudaGetSymbolAddress(&p, g_h1 ); h1  = (float*)p;
    cudaGetSymbolAddress(&p, g_xw2); xw2 = (float*)p;
    cudaGetSymbolAddress(&p, g_h2 ); h2  = (float*)p;
    cudaGetSymbolAddress(&p, g_xw3); xw3 = (float*)p;
    cudaGetSymbolAddress(&p, g_a1 ); a1  = (float*)p;
    cudaGetSymbolAddress(&p, g_a2 ); a2  = (float*)p;
    cudaGetSymbolAddress(&p, g_w1t); w1t = (float*)p;
    cudaGetSymbolAddress(&p, g_w2t); w2t = (float*)p;

    const int smem1 = 2 * (128 + 128) * 36 * 4;  // 73728
    const int smem2 = 2 * (128 + 64) * 36 * 4;   // 55296
    cudaFuncSetAttribute(rgemm_cp<128, 256>,
                         cudaFuncAttributeMaxDynamicSharedMemorySize, smem1);
    cudaFuncSetAttribute(rgemm_cp<64, 128>,
                         cudaFuncAttributeMaxDynamicSharedMemorySize, smem2);

    // ---- pre-pass: round inputs/weights ----
    round_tf32<false><<<(N_NODES * D0 / 4 + 255) / 256, 256>>>(
        b_z, a1, (size_t)N_NODES * D0 / 4);
    transpose_w<D0, D1><<<dim3((D0 * D1 + 255) / 256, N_REL), 256>>>(W1, w1t);
    transpose_w<D1, D2><<<dim3((D1 * D2 + 255) / 256, N_REL), 256>>>(W2, w2t);

    // ---- layer 1: xw1[r] = a1 @ w1t[r]^T; h1 = bias1 + scatter ----
    rgemm_cp<128, 256>
        <<<dim3(N_REL, N_NODES / 128), 256, smem1>>>(a1, w1t, xw1);
    init_bias<D1><<<(N_NODES * D1 + 255) / 256, 256>>>(h1, b1);
    edge_scatter<D1><<<N_EDGES / 8, 256>>>(xw1, eidx, ew, et, h1);

    // ---- layer 2: a2 = round(relu(h1)); xw2[r] = a2 @ w2t[r]^T ----
    round_tf32<true><<<(N_NODES * D1 / 4 + 255) / 256, 256>>>(
        h1, a2, (size_t)N_NODES * D1 / 4);
    rgemm_cp<64, 128>
        <<<dim3(N_REL, N_NODES / 128), 256, smem2>>>(a2, w2t, xw2);
    init_bias<D2><<<(N_NODES * D2 + 255) / 256, 256>>>(h2, b2);
    edge_scatter<D2><<<N_EDGES / 16, 256>>>(xw2, eidx, ew, et, h2);

    // ---- layer 3: xw3[r,n] = relu(h2[n]) . W3[r]; out = bias3 + scatter ----
    gemm3_kernel<<<(N_NODES + 255) / 256, 256>>>(h2, W3, xw3);
    init_out<<<(N_NODES + 255) / 256, 256>>>(out, b3);
    edge_scatter1<<<N_EDGES / 256, 256>>>(xw3, eidx, ew, et, out);
}

// round 10
// speedup vs baseline: 2.5669x; 1.0202x over previous
#include <cuda_runtime.h>
#include <cstdint>
#include <cstddef>

#define N_NODES 102400
#define N_EDGES 1638400
#define N_REL   8
#define D0      256
#define D1      128
#define D2      64

// ---------------- scratch (device globals; no allocation allowed) ----------
__device__ __align__(16) float g_xw1[(size_t)N_REL * N_NODES * D1]; // 419 MB
__device__ __align__(16) float g_h1 [(size_t)N_NODES * D1];         // 52 MB
__device__ __align__(16) float g_xw2[(size_t)N_REL * N_NODES * D2]; // 210 MB
__device__ __align__(16) float g_h2 [(size_t)N_NODES * D2];         // 26 MB
__device__ __align__(16) float g_xw3[(size_t)N_REL * N_NODES];      // 3.3 MB
__device__ __align__(16) float g_a1 [(size_t)N_NODES * D0];         // 105 MB (tf32 b_z)
__device__ __align__(16) float g_a2 [(size_t)N_NODES * D1];         // 52 MB (tf32 relu h1)
__device__ __align__(16) float g_w1t[(size_t)N_REL * D1 * D0];      // 1 MB  [r][n][k]
__device__ __align__(16) float g_w2t[(size_t)N_REL * D2 * D1];      // 0.25 MB

__device__ __forceinline__ float to_tf32(float x) {
    float y;
    asm("cvt.rna.tf32.f32 %0, %1;" : "=f"(y) : "f"(x));
    return y;
}

__device__ __forceinline__ void mma_tf32(float* c, const uint32_t* a,
                                         uint32_t b0, uint32_t b1) {
    asm volatile(
        "mma.sync.aligned.m16n8k8.row.col.f32.tf32.tf32.f32 "
        "{%0,%1,%2,%3}, {%4,%5,%6,%7}, {%8,%9}, {%0,%1,%2,%3};"
        : "+f"(c[0]), "+f"(c[1]), "+f"(c[2]), "+f"(c[3])
        : "r"(a[0]), "r"(a[1]), "r"(a[2]), "r"(a[3]), "r"(b0), "r"(b1));
}

__device__ __forceinline__ void ldsm_x4(uint32_t* r, uint32_t saddr) {
    asm volatile(
        "ldmatrix.sync.aligned.m8n8.x4.shared.b16 {%0,%1,%2,%3}, [%4];"
        : "=r"(r[0]), "=r"(r[1]), "=r"(r[2]), "=r"(r[3]) : "r"(saddr));
}

__device__ __forceinline__ uint32_t smem_u32(const void* p) {
    return (uint32_t)__cvta_generic_to_shared(p);
}

__device__ __forceinline__ void red_add_v4(float* addr, float a, float b,
                                           float c, float d) {
    asm volatile("red.global.add.v4.f32 [%0], {%1, %2, %3, %4};"
                 :: "l"(addr), "f"(a), "f"(b), "f"(c), "f"(d) : "memory");
}

#define CP_ASYNC16(dst, src) \
    asm volatile("cp.async.cg.shared.global [%0], [%1], 16;" \
                 :: "r"(dst), "l"(src) : "memory")
#define CP_COMMIT() asm volatile("cp.async.commit_group;" ::: "memory")
#define CP_WAIT(n)  asm volatile("cp.async.wait_group %0;" :: "n"(n) : "memory")

// ============== cp.async 3-buffer tf32 batched GEMM ========================
// C[r] = A @ Bt[r]^T;  A:[N_NODES,Kdim] (pre-rounded tf32), Bt:[R][BN][Kdim]
// (pre-rounded + pre-transposed). blockIdx.x = relation, blockIdx.y = M tile.
// 256 threads = 8 warps as 4(M) x 2(N). 3 smem buffers, ONE sync per chunk:
//   wait_group(1); sync; issue load(c+2) into (c+2)%3 (== (c-1)%3, consumed
//   last iter, safe after this sync); compute chunk c.
// PAD=36 (144B rows): 16B-aligned for cp.async, conflict-free for ldmatrix.
template<int BN, int Kdim>
__global__ __launch_bounds__(256)
void rgemm_cp(const float* __restrict__ A, const float* __restrict__ Bt,
              float* __restrict__ C) {
    constexpr int BM = 128, BK = 32, PAD = 36;
    constexpr int NCH = Kdim / BK;
    constexpr int WN = BN / 2, NT = WN / 8, NP = NT / 2;
    constexpr int ASTR = BM * PAD;          // floats per A stage
    constexpr int BSTR = BN * PAD;

    extern __shared__ __align__(16) float sm[];
    float* Asm = sm;                        // [3][BM][PAD]
    float* Bsm = sm + 3 * ASTR;             // [3][BN][PAD]

    const int r   = blockIdx.x;
    const int m0  = blockIdx.y * BM;
    const int tid = threadIdx.x;
    const int lane = tid & 31, wid = tid >> 5;
    const int mi = wid & 3, ni = wid >> 2;
    const int g = lane >> 2, t = lane & 3;

    const float* Ab = A + (size_t)m0 * Kdim;
    const float* Bb = Bt + (size_t)r * BN * Kdim;
    float*       Cr = C + (size_t)r * N_NODES * BN + (size_t)m0 * BN;

    // ---- ldmatrix per-thread addresses (stage 0; add stage/kk offsets) ----
    const int j8 = lane >> 3, i8 = lane & 7;
    uint32_t aAddr[2];
#pragma unroll
    for (int mt = 0; mt < 2; mt++) {
        int row = mi * 32 + mt * 16 + (j8 & 1) * 8 + i8;
        aAddr[mt] = smem_u32(&Asm[row * PAD]) + (j8 >> 1) * 16;
    }
    uint32_t bAddr[NP];
#pragma unroll
    for (int p = 0; p < NP; p++) {
        int nrow = ni * WN + p * 16 + (j8 >> 1) * 8 + i8;
        bAddr[p] = smem_u32(&Bsm[nrow * PAD]) + (j8 & 1) * 16;
    }

    // ---- tile loader: raw 16B cp.async copies (data pre-rounded) ----
    auto load_stage = [&](int c, int s) {
        float* Ad = Asm + s * ASTR;
#pragma unroll
        for (int i = 0; i < 4; i++) {
            int idx = i * 256 + tid;
            int row = idx >> 3, ch = (idx & 7) * 4;
            CP_ASYNC16(smem_u32(Ad + row * PAD + ch),
                       Ab + (size_t)row * Kdim + c * BK + ch);
        }
        float* Bd = Bsm + s * BSTR;
#pragma unroll
        for (int i = 0; i < BN / 32; i++) {
            int idx = i * 256 + tid;
            int row = idx >> 3, ch = (idx & 7) * 4;
            CP_ASYNC16(smem_u32(Bd + row * PAD + ch),
                       Bb + (size_t)row * Kdim + c * BK + ch);
        }
        CP_COMMIT();
    };

    float acc[2][NT][4];
#pragma unroll
    for (int mt = 0; mt < 2; mt++)
#pragma unroll
        for (int nt = 0; nt < NT; nt++)
#pragma unroll
            for (int q = 0; q < 4; q++) acc[mt][nt][q] = 0.f;

    load_stage(0, 0);
    load_stage(1, 1);

    for (int c = 0; c < NCH; c++) {
        const int s = c % 3;
        CP_WAIT(1);                 // chunk c resident (one group may fly)
        __syncthreads();
        if (c + 2 < NCH) load_stage(c + 2, (c + 2) % 3);
        else CP_COMMIT();           // keep group accounting uniform

        const uint32_t ao = (uint32_t)s * ASTR * 4, bo = (uint32_t)s * BSTR * 4;
#pragma unroll
        for (int kk = 0; kk < 4; kk++) {
            uint32_t a[2][4];
            ldsm_x4(a[0], aAddr[0] + ao + kk * 32);
            ldsm_x4(a[1], aAddr[1] + ao + kk * 32);
#pragma unroll
            for (int p = 0; p < NP; p++) {
                uint32_t b[4];
                ldsm_x4(b, bAddr[p] + bo + kk * 32);
#pragma unroll
                for (int mt = 0; mt < 2; mt++) {
                    mma_tf32(acc[mt][2 * p],     a[mt], b[0], b[1]);
                    mma_tf32(acc[mt][2 * p + 1], a[mt], b[2], b[3]);
                }
            }
        }
    }

    // ---- epilogue: float2 stores straight to gmem ----
#pragma unroll
    for (int mt = 0; mt < 2; mt++) {
        int row = mi * 32 + mt * 16 + g;
#pragma unroll
        for (int nt = 0; nt < NT; nt++) {
            int col = ni * WN + nt * 8 + t * 2;
            *(float2*)&Cr[(size_t)row * BN + col] =
                make_float2(acc[mt][nt][0], acc[mt][nt][1]);
            *(float2*)&Cr[(size_t)(row + 8) * BN + col] =
                make_float2(acc[mt][nt][2], acc[mt][nt][3]);
        }
    }
}

// ---------------- pre-pass: tf32 rounding (+optional relu) -----------------
template<bool RELU>
__global__ void round_tf32(const float* __restrict__ src,
                           float* __restrict__ dst, size_t n4) {
    size_t i = (size_t)blockIdx.x * blockDim.x + threadIdx.x;
    if (i >= n4) return;
    float4 v = *(const float4*)(src + i * 4);
    if (RELU) {
        v.x = fmaxf(v.x, 0.f); v.y = fmaxf(v.y, 0.f);
        v.z = fmaxf(v.z, 0.f); v.w = fmaxf(v.w, 0.f);
    }
    v.x = to_tf32(v.x); v.y = to_tf32(v.y);
    v.z = to_tf32(v.z); v.w = to_tf32(v.w);
    *(float4*)(dst + i * 4) = v;
}

// W[r][k][n] -> Wt[r][n][k], tf32-rounded
template<int K, int N>
__global__ void transpose_w(const float* __restrict__ W,
                            float* __restrict__ Wt) {
    int r = blockIdx.y;
    int idx = blockIdx.x * 256 + threadIdx.x;
    if (idx >= K * N) return;
    int k = idx / N, n = idx % N;
    Wt[((size_t)r * N + n) * K + k] = to_tf32(W[((size_t)r * K + k) * N + n]);
}

// ---------------- layer-3 transform: xw3[r,n] = relu(h2[n]) . W3[r] --------
__global__ void gemm3_kernel(const float* __restrict__ h2,
                             const float* __restrict__ W3,
                             float* __restrict__ xw3) {
    __shared__ float w[N_REL][D2];
    for (int i = threadIdx.x; i < N_REL * D2; i += blockDim.x)
        w[i / D2][i % D2] = W3[i];
    __syncthreads();

    int n = blockIdx.x * blockDim.x + threadIdx.x;
    if (n >= N_NODES) return;

    float acc[N_REL];
#pragma unroll
    for (int r = 0; r < N_REL; r++) acc[r] = 0.f;

    const float4* hp = (const float4*)&h2[(size_t)n * D2];
#pragma unroll
    for (int k4 = 0; k4 < D2 / 4; k4++) {
        float4 v = hp[k4];
        v.x = fmaxf(v.x, 0.f); v.y = fmaxf(v.y, 0.f);
        v.z = fmaxf(v.z, 0.f); v.w = fmaxf(v.w, 0.f);
#pragma unroll
        for (int r = 0; r < N_REL; r++) {
            acc[r] += v.x * w[r][k4 * 4 + 0];
            acc[r] += v.y * w[r][k4 * 4 + 1];
            acc[r] += v.z * w[r][k4 * 4 + 2];
            acc[r] += v.w * w[r][k4 * 4 + 3];
        }
    }
#pragma unroll
    for (int r = 0; r < N_REL; r++)
        xw3[(size_t)r * N_NODES + n] = acc[r];
}

// ---------------- bias init ------------------------------------------------
template<int D>
__global__ void init_bias(float* __restrict__ h, const float* __restrict__ bias) {
    size_t i = (size_t)blockIdx.x * blockDim.x + threadIdx.x;
    if (i < (size_t)N_NODES * D) h[i] = bias[i & (D - 1)];
}

__global__ void init_out(float* __restrict__ out, const float* __restrict__ b3) {
    int i = blockIdx.x * blockDim.x + threadIdx.x;
    if (i < N_NODES) out[i] = b3[0];
}

// ---------------- edge scatter: h[dst] += xw[etype, src] * ew --------------
template<int D>
__global__ void edge_scatter(const float* __restrict__ xw,
                             const int* __restrict__ eidx,
                             const float* __restrict__ ew,
                             const int* __restrict__ et,
                             float* __restrict__ h) {
    constexpr int LPE = D / 4;        // lanes per edge
    constexpr int EPW = 32 / LPE;     // edges per warp
    int warp = (blockIdx.x * blockDim.x + threadIdx.x) >> 5;
    int lane = threadIdx.x & 31;
    int e = warp * EPW + lane / LPE;
    if (e >= N_EDGES) return;
    int sub = (lane % LPE) * 4;

    int   src = eidx[e];
    int   dst = eidx[N_EDGES + e];
    int   t   = et[e];
    float w   = ew[e];

    float4 v = *(const float4*)&xw[((size_t)t * N_NODES + (size_t)src) * D + sub];
    float* o = &h[(size_t)dst * D + sub];
    red_add_v4(o, v.x * w, v.y * w, v.z * w, v.w * w);
}

__global__ void edge_scatter1(const float* __restrict__ xw3,
                              const int* __restrict__ eidx,
                              const float* __restrict__ ew,
                              const int* __restrict__ et,
                              float* __restrict__ out) {
    int e = blockIdx.x * blockDim.x + threadIdx.x;
    if (e >= N_EDGES) return;
    int src = eidx[e];
    int dst = eidx[N_EDGES + e];
    int t   = et[e];
    atomicAdd(&out[dst], xw3[(size_t)t * N_NODES + (size_t)src] * ew[e]);
}

// ---------------- launcher --------------------------------------------------
extern "C" void kernel_launch(void* const* d_in, const int* in_sizes, int n_in,
                              void* d_out, int out_size) {
    const float* b_z  = (const float*)d_in[0];
    const int*   eidx = (const int*)d_in[1];
    const float* ew   = (const float*)d_in[2];
    const int*   et   = (const int*)d_in[3];
    const float* W1   = (const float*)d_in[4];
    const float* b1   = (const float*)d_in[5];
    const float* W2   = (const float*)d_in[6];
    const float* b2   = (const float*)d_in[7];
    const float* W3   = (const float*)d_in[8];
    const float* b3   = (const float*)d_in[9];
    float*       out  = (float*)d_out;

    void* p;
    float *xw1, *h1, *xw2, *h2, *xw3, *a1, *a2, *w1t, *w2t;
    cudaGetSymbolAddress(&p, g_xw1); xw1 = (float*)p;
    cudaGetSymbolAddress(&p, g_h1 ); h1  = (float*)p;
    cudaGetSymbolAddress(&p, g_xw2); xw2 = (float*)p;
    cudaGetSymbolAddress(&p, g_h2 ); h2  = (float*)p;
    cudaGetSymbolAddress(&p, g_xw3); xw3 = (float*)p;
    cudaGetSymbolAddress(&p, g_a1 ); a1  = (float*)p;
    cudaGetSymbolAddress(&p, g_a2 ); a2  = (float*)p;
    cudaGetSymbolAddress(&p, g_w1t); w1t = (float*)p;
    cudaGetSymbolAddress(&p, g_w2t); w2t = (float*)p;

    const int smem1 = 3 * (128 + 128) * 36 * 4;  // 110592
    const int smem2 = 3 * (128 + 64) * 36 * 4;   // 82944
    cudaFuncSetAttribute(rgemm_cp<128, 256>,
                         cudaFuncAttributeMaxDynamicSharedMemorySize, smem1);
    cudaFuncSetAttribute(rgemm_cp<64, 128>,
                         cudaFuncAttributeMaxDynamicSharedMemorySize, smem2);

    // ---- pre-pass: round inputs/weights ----
    round_tf32<false><<<(N_NODES * D0 / 4 + 255) / 256, 256>>>(
        b_z, a1, (size_t)N_NODES * D0 / 4);
    transpose_w<D0, D1><<<dim3((D0 * D1 + 255) / 256, N_REL), 256>>>(W1, w1t);
    transpose_w<D1, D2><<<dim3((D1 * D2 + 255) / 256, N_REL), 256>>>(W2, w2t);

    // ---- layer 1: xw1[r] = a1 @ w1t[r]^T; h1 = bias1 + scatter ----
    rgemm_cp<128, 256>
        <<<dim3(N_REL, N_NODES / 128), 256, smem1>>>(a1, w1t, xw1);
    init_bias<D1><<<(N_NODES * D1 + 255) / 256, 256>>>(h1, b1);
    edge_scatter<D1><<<N_EDGES / 8, 256>>>(xw1, eidx, ew, et, h1);

    // ---- layer 2: a2 = round(relu(h1)); xw2[r] = a2 @ w2t[r]^T ----
    round_tf32<true><<<(N_NODES * D1 / 4 + 255) / 256, 256>>>(
        h1, a2, (size_t)N_NODES * D1 / 4);
    rgemm_cp<64, 128>
        <<<dim3(N_REL, N_NODES / 128), 256, smem2>>>(a2, w2t, xw2);
    init_bias<D2><<<(N_NODES * D2 + 255) / 256, 256>>>(h2, b2);
    edge_scatter<D2><<<N_EDGES / 16, 256>>>(xw2, eidx, ew, et, h2);

    // ---- layer 3: xw3[r,n] = relu(h2[n]) . W3[r]; out = bias3 + scatter ----
    gemm3_kernel<<<(N_NODES + 255) / 256, 256>>>(h2, W3, xw3);
    init_out<<<(N_NODES + 255) / 256, 256>>>(out, b3);
    edge_scatter1<<<N_EDGES / 256, 256>>>(xw3, eidx, ew, et, out);
}

// round 11
// speedup vs baseline: 2.5911x; 1.0094x over previous
#include <cuda_runtime.h>
#include <cstdint>
#include <cstddef>

#define N_NODES 102400
#define N_EDGES 1638400
#define N_REL   8
#define D0      256
#define D1      128
#define D2      64

// ---------------- scratch (device globals; no allocation allowed) ----------
__device__ __align__(16) float g_xw1[(size_t)N_REL * N_NODES * D1]; // 419 MB
__device__ __align__(16) float g_h1 [(size_t)N_NODES * D1];         // 52 MB
__device__ __align__(16) float g_xw2[(size_t)N_REL * N_NODES * D2]; // 210 MB
__device__ __align__(16) float g_h2 [(size_t)N_NODES * D2];         // 26 MB
__device__ __align__(16) float g_xw3[(size_t)N_REL * N_NODES];      // 3.3 MB
__device__ __align__(16) float g_w1t[(size_t)N_REL * D1 * D0];      // 1 MB  [r][n][k]
__device__ __align__(16) float g_w2t[(size_t)N_REL * D2 * D1];      // 0.25 MB

__device__ __forceinline__ float to_tf32(float x) {
    float y;
    asm("cvt.rna.tf32.f32 %0, %1;" : "=f"(y) : "f"(x));
    return y;
}

__device__ __forceinline__ void mma_tf32(float* c, const uint32_t* a,
                                         uint32_t b0, uint32_t b1) {
    asm volatile(
        "mma.sync.aligned.m16n8k8.row.col.f32.tf32.tf32.f32 "
        "{%0,%1,%2,%3}, {%4,%5,%6,%7}, {%8,%9}, {%0,%1,%2,%3};"
        : "+f"(c[0]), "+f"(c[1]), "+f"(c[2]), "+f"(c[3])
        : "r"(a[0]), "r"(a[1]), "r"(a[2]), "r"(a[3]), "r"(b0), "r"(b1));
}

__device__ __forceinline__ void ldsm_x4(uint32_t* r, uint32_t saddr) {
    asm volatile(
        "ldmatrix.sync.aligned.m8n8.x4.shared.b16 {%0,%1,%2,%3}, [%4];"
        : "=r"(r[0]), "=r"(r[1]), "=r"(r[2]), "=r"(r[3]) : "r"(saddr));
}

__device__ __forceinline__ uint32_t smem_u32(const void* p) {
    return (uint32_t)__cvta_generic_to_shared(p);
}

__device__ __forceinline__ void red_add_v4(float* addr, float a, float b,
                                           float c, float d) {
    asm volatile("red.global.add.v4.f32 [%0], {%1, %2, %3, %4};"
                 :: "l"(addr), "f"(a), "f"(b), "f"(c), "f"(d) : "memory");
}

#define CP_ASYNC16(dst, src) \
    asm volatile("cp.async.cg.shared.global [%0], [%1], 16;" \
                 :: "r"(dst), "l"(src) : "memory")
#define CP_COMMIT() asm volatile("cp.async.commit_group;" ::: "memory")
#define CP_WAIT(n)  asm volatile("cp.async.wait_group %0;" :: "n"(n) : "memory")

// ============== cp.async 3-buffer tf32 batched GEMM ========================
// C[r] = (relu?)A @ Bt[r]^T;  A:[N_NODES,Kdim] raw fp32, Bt:[R][BN][Kdim]
// (pre-rounded tf32 + pre-transposed). relu + tf32 rounding of A applied
// IN REGISTERS after ldmatrix (identical values to pre-rounding, no pre-pass).
// blockIdx.x = relation, blockIdx.y = M tile. 256 threads = 8 warps 4(M)x2(N).
// 3 smem buffers, one sync per chunk (load c+2 overlaps compute c, c+1).
// PAD=36 (144B rows): 16B-aligned for cp.async, conflict-free for ldmatrix.
template<int BN, int Kdim, bool RELU>
__global__ __launch_bounds__(256)
void rgemm_cp(const float* __restrict__ A, const float* __restrict__ Bt,
              float* __restrict__ C) {
    constexpr int BM = 128, BK = 32, PAD = 36;
    constexpr int NCH = Kdim / BK;
    constexpr int WN = BN / 2, NT = WN / 8, NP = NT / 2;
    constexpr int ASTR = BM * PAD;          // floats per A stage
    constexpr int BSTR = BN * PAD;

    extern __shared__ __align__(16) float sm[];
    float* Asm = sm;                        // [3][BM][PAD]
    float* Bsm = sm + 3 * ASTR;             // [3][BN][PAD]

    const int r   = blockIdx.x;
    const int m0  = blockIdx.y * BM;
    const int tid = threadIdx.x;
    const int lane = tid & 31, wid = tid >> 5;
    const int mi = wid & 3, ni = wid >> 2;
    const int g = lane >> 2, t = lane & 3;

    const float* Ab = A + (size_t)m0 * Kdim;
    const float* Bb = Bt + (size_t)r * BN * Kdim;
    float*       Cr = C + (size_t)r * N_NODES * BN + (size_t)m0 * BN;

    // ---- ldmatrix per-thread addresses (stage 0; add stage/kk offsets) ----
    const int j8 = lane >> 3, i8 = lane & 7;
    uint32_t aAddr[2];
#pragma unroll
    for (int mt = 0; mt < 2; mt++) {
        int row = mi * 32 + mt * 16 + (j8 & 1) * 8 + i8;
        aAddr[mt] = smem_u32(&Asm[row * PAD]) + (j8 >> 1) * 16;
    }
    uint32_t bAddr[NP];
#pragma unroll
    for (int p = 0; p < NP; p++) {
        int nrow = ni * WN + p * 16 + (j8 >> 1) * 8 + i8;
        bAddr[p] = smem_u32(&Bsm[nrow * PAD]) + (j8 & 1) * 16;
    }

    // ---- tile loader: raw 16B cp.async copies ----
    auto load_stage = [&](int c, int s) {
        float* Ad = Asm + s * ASTR;
#pragma unroll
        for (int i = 0; i < 4; i++) {
            int idx = i * 256 + tid;
            int row = idx >> 3, ch = (idx & 7) * 4;
            CP_ASYNC16(smem_u32(Ad + row * PAD + ch),
                       Ab + (size_t)row * Kdim + c * BK + ch);
        }
        float* Bd = Bsm + s * BSTR;
#pragma unroll
        for (int i = 0; i < BN / 32; i++) {
            int idx = i * 256 + tid;
            int row = idx >> 3, ch = (idx & 7) * 4;
            CP_ASYNC16(smem_u32(Bd + row * PAD + ch),
                       Bb + (size_t)row * Kdim + c * BK + ch);
        }
        CP_COMMIT();
    };

    float acc[2][NT][4];
#pragma unroll
    for (int mt = 0; mt < 2; mt++)
#pragma unroll
        for (int nt = 0; nt < NT; nt++)
#pragma unroll
            for (int q = 0; q < 4; q++) acc[mt][nt][q] = 0.f;

    load_stage(0, 0);
    load_stage(1, 1);

    for (int c = 0; c < NCH; c++) {
        const int s = c % 3;
        CP_WAIT(1);                 // chunk c resident (one group may fly)
        __syncthreads();
        if (c + 2 < NCH) load_stage(c + 2, (c + 2) % 3);
        else CP_COMMIT();           // keep group accounting uniform

        const uint32_t ao = (uint32_t)s * ASTR * 4, bo = (uint32_t)s * BSTR * 4;
#pragma unroll
        for (int kk = 0; kk < 4; kk++) {
            uint32_t a[2][4];
            ldsm_x4(a[0], aAddr[0] + ao + kk * 32);
            ldsm_x4(a[1], aAddr[1] + ao + kk * 32);
            // in-register relu + tf32 rounding of A fragments
#pragma unroll
            for (int mt = 0; mt < 2; mt++)
#pragma unroll
                for (int q = 0; q < 4; q++) {
                    float x = __uint_as_float(a[mt][q]);
                    if (RELU) x = fmaxf(x, 0.f);
                    a[mt][q] = __float_as_uint(to_tf32(x));
                }
#pragma unroll
            for (int p = 0; p < NP; p++) {
                uint32_t b[4];
                ldsm_x4(b, bAddr[p] + bo + kk * 32);
#pragma unroll
                for (int mt = 0; mt < 2; mt++) {
                    mma_tf32(acc[mt][2 * p],     a[mt], b[0], b[1]);
                    mma_tf32(acc[mt][2 * p + 1], a[mt], b[2], b[3]);
                }
            }
        }
    }

    // ---- epilogue: float2 stores straight to gmem ----
#pragma unroll
    for (int mt = 0; mt < 2; mt++) {
        int row = mi * 32 + mt * 16 + g;
#pragma unroll
        for (int nt = 0; nt < NT; nt++) {
            int col = ni * WN + nt * 8 + t * 2;
            *(float2*)&Cr[(size_t)row * BN + col] =
                make_float2(acc[mt][nt][0], acc[mt][nt][1]);
            *(float2*)&Cr[(size_t)(row + 8) * BN + col] =
                make_float2(acc[mt][nt][2], acc[mt][nt][3]);
        }
    }
}

// W[r][k][n] -> Wt[r][n][k], tf32-rounded
template<int K, int N>
__global__ void transpose_w(const float* __restrict__ W,
                            float* __restrict__ Wt) {
    int r = blockIdx.y;
    int idx = blockIdx.x * 256 + threadIdx.x;
    if (idx >= K * N) return;
    int k = idx / N, n = idx % N;
    Wt[((size_t)r * N + n) * K + k] = to_tf32(W[((size_t)r * K + k) * N + n]);
}

// ---------------- layer-3 transform: xw3[r,n] = relu(h2[n]) . W3[r] --------
__global__ void gemm3_kernel(const float* __restrict__ h2,
                             const float* __restrict__ W3,
                             float* __restrict__ xw3) {
    __shared__ float w[N_REL][D2];
    for (int i = threadIdx.x; i < N_REL * D2; i += blockDim.x)
        w[i / D2][i % D2] = W3[i];
    __syncthreads();

    int n = blockIdx.x * blockDim.x + threadIdx.x;
    if (n >= N_NODES) return;

    float acc[N_REL];
#pragma unroll
    for (int r = 0; r < N_REL; r++) acc[r] = 0.f;

    const float4* hp = (const float4*)&h2[(size_t)n * D2];
#pragma unroll
    for (int k4 = 0; k4 < D2 / 4; k4++) {
        float4 v = hp[k4];
        v.x = fmaxf(v.x, 0.f); v.y = fmaxf(v.y, 0.f);
        v.z = fmaxf(v.z, 0.f); v.w = fmaxf(v.w, 0.f);
#pragma unroll
        for (int r = 0; r < N_REL; r++) {
            acc[r] += v.x * w[r][k4 * 4 + 0];
            acc[r] += v.y * w[r][k4 * 4 + 1];
            acc[r] += v.z * w[r][k4 * 4 + 2];
            acc[r] += v.w * w[r][k4 * 4 + 3];
        }
    }
#pragma unroll
    for (int r = 0; r < N_REL; r++)
        xw3[(size_t)r * N_NODES + n] = acc[r];
}

// ---------------- bias init ------------------------------------------------
template<int D>
__global__ void init_bias(float* __restrict__ h, const float* __restrict__ bias) {
    size_t i = (size_t)blockIdx.x * blockDim.x + threadIdx.x;
    if (i < (size_t)N_NODES * D) h[i] = bias[i & (D - 1)];
}

__global__ void init_out(float* __restrict__ out, const float* __restrict__ b3) {
    int i = blockIdx.x * blockDim.x + threadIdx.x;
    if (i < N_NODES) out[i] = b3[0];
}

// ---------------- edge scatter: h[dst] += xw[etype, src] * ew --------------
template<int D>
__global__ void edge_scatter(const float* __restrict__ xw,
                             const int* __restrict__ eidx,
                             const float* __restrict__ ew,
                             const int* __restrict__ et,
                             float* __restrict__ h) {
    constexpr int LPE = D / 4;        // lanes per edge
    constexpr int EPW = 32 / LPE;     // edges per warp
    int warp = (blockIdx.x * blockDim.x + threadIdx.x) >> 5;
    int lane = threadIdx.x & 31;
    int e = warp * EPW + lane / LPE;
    if (e >= N_EDGES) return;
    int sub = (lane % LPE) * 4;

    int   src = eidx[e];
    int   dst = eidx[N_EDGES + e];
    int   t   = et[e];
    float w   = ew[e];

    float4 v = *(const float4*)&xw[((size_t)t * N_NODES + (size_t)src) * D + sub];
    float* o = &h[(size_t)dst * D + sub];
    red_add_v4(o, v.x * w, v.y * w, v.z * w, v.w * w);
}

__global__ void edge_scatter1(const float* __restrict__ xw3,
                              const int* __restrict__ eidx,
                              const float* __restrict__ ew,
                              const int* __restrict__ et,
                              float* __restrict__ out) {
    int e = blockIdx.x * blockDim.x + threadIdx.x;
    if (e >= N_EDGES) return;
    int src = eidx[e];
    int dst = eidx[N_EDGES + e];
    int t   = et[e];
    atomicAdd(&out[dst], xw3[(size_t)t * N_NODES + (size_t)src] * ew[e]);
}

// ---------------- launcher --------------------------------------------------
extern "C" void kernel_launch(void* const* d_in, const int* in_sizes, int n_in,
                              void* d_out, int out_size) {
    const float* b_z  = (const float*)d_in[0];
    const int*   eidx = (const int*)d_in[1];
    const float* ew   = (const float*)d_in[2];
    const int*   et   = (const int*)d_in[3];
    const float* W1   = (const float*)d_in[4];
    const float* b1   = (const float*)d_in[5];
    const float* W2   = (const float*)d_in[6];
    const float* b2   = (const float*)d_in[7];
    const float* W3   = (const float*)d_in[8];
    const float* b3   = (const float*)d_in[9];
    float*       out  = (float*)d_out;

    void* p;
    float *xw1, *h1, *xw2, *h2, *xw3, *w1t, *w2t;
    cudaGetSymbolAddress(&p, g_xw1); xw1 = (float*)p;
    cudaGetSymbolAddress(&p, g_h1 ); h1  = (float*)p;
    cudaGetSymbolAddress(&p, g_xw2); xw2 = (float*)p;
    cudaGetSymbolAddress(&p, g_h2 ); h2  = (float*)p;
    cudaGetSymbolAddress(&p, g_xw3); xw3 = (float*)p;
    cudaGetSymbolAddress(&p, g_w1t); w1t = (float*)p;
    cudaGetSymbolAddress(&p, g_w2t); w2t = (float*)p;

    const int smem1 = 3 * (128 + 128) * 36 * 4;  // 110592
    const int smem2 = 3 * (128 + 64) * 36 * 4;   // 82944
    cudaFuncSetAttribute(rgemm_cp<128, 256, false>,
                         cudaFuncAttributeMaxDynamicSharedMemorySize, smem1);
    cudaFuncSetAttribute(rgemm_cp<64, 128, true>,
                         cudaFuncAttributeMaxDynamicSharedMemorySize, smem2);

    // ---- pre-pass: round + transpose weights (tiny) ----
    transpose_w<D0, D1><<<dim3((D0 * D1 + 255) / 256, N_REL), 256>>>(W1, w1t);
    transpose_w<D1, D2><<<dim3((D1 * D2 + 255) / 256, N_REL), 256>>>(W2, w2t);

    // ---- layer 1: xw1[r] = b_z @ w1t[r]^T; h1 = bias1 + scatter ----
    rgemm_cp<128, 256, false>
        <<<dim3(N_REL, N_NODES / 128), 256, smem1>>>(b_z, w1t, xw1);
    init_bias<D1><<<(N_NODES * D1 + 255) / 256, 256>>>(h1, b1);
    edge_scatter<D1><<<N_EDGES / 8, 256>>>(xw1, eidx, ew, et, h1);

    // ---- layer 2: xw2[r] = relu(h1) @ w2t[r]^T; h2 = bias2 + scatter ----
    rgemm_cp<64, 128, true>
        <<<dim3(N_REL, N_NODES / 128), 256, smem2>>>(h1, w2t, xw2);
    init_bias<D2><<<(N_NODES * D2 + 255) / 256, 256>>>(h2, b2);
    edge_scatter<D2><<<N_EDGES / 16, 256>>>(xw2, eidx, ew, et, h2);

    // ---- layer 3: xw3[r,n] = relu(h2[n]) . W3[r]; out = bias3 + scatter ----
    gemm3_kernel<<<(N_NODES + 255) / 256, 256>>>(h2, W3, xw3);
    init_out<<<(N_NODES + 255) / 256, 256>>>(out, b3);
    edge_scatter1<<<N_EDGES / 256, 256>>>(xw3, eidx, ew, et, out);
}

// round 12
// speedup vs baseline: 3.2967x; 1.2723x over previous
#include <cuda_runtime.h>
#include <cstdint>
#include <cstddef>

#define N_NODES 102400
#define N_EDGES 1638400
#define N_REL   8
#define D0      256
#define D1      128
#define D2      64

// ---------------- scratch (device globals; no allocation allowed) ----------
__device__ __align__(16) float g_xw1[(size_t)N_REL * N_NODES * D1]; // 419 MB
__device__ __align__(16) float g_h1 [(size_t)N_NODES * D1];         // 52 MB (relu'd)
__device__ __align__(16) float g_xw2[(size_t)N_REL * N_NODES * D2]; // 210 MB
__device__ __align__(16) float g_h2 [(size_t)N_NODES * D2];         // 26 MB (relu'd)
__device__ __align__(16) float g_xw3[(size_t)N_REL * N_NODES];      // 3.3 MB
__device__ __align__(16) float g_w1t[(size_t)N_REL * D1 * D0];      // 1 MB [r][n][k]
__device__ __align__(16) float g_w2t[(size_t)N_REL * D2 * D1];      // 0.25 MB

// CSR-by-dst edge structure (rebuilt every call; zero atomic scatters later)
__device__ int      g_deg[N_NODES];
__device__ int      g_fil[N_NODES];
__device__ int      g_off[N_NODES + 1];
__device__ int      g_bsum[400];
__device__ uint32_t g_es [N_EDGES];   // src | (t << 20)
__device__ float    g_ewb[N_EDGES];

__device__ __forceinline__ float to_tf32(float x) {
    float y;
    asm("cvt.rna.tf32.f32 %0, %1;" : "=f"(y) : "f"(x));
    return y;
}

__device__ __forceinline__ void mma_tf32(float* c, const uint32_t* a,
                                         uint32_t b0, uint32_t b1) {
    asm volatile(
        "mma.sync.aligned.m16n8k8.row.col.f32.tf32.tf32.f32 "
        "{%0,%1,%2,%3}, {%4,%5,%6,%7}, {%8,%9}, {%0,%1,%2,%3};"
        : "+f"(c[0]), "+f"(c[1]), "+f"(c[2]), "+f"(c[3])
        : "r"(a[0]), "r"(a[1]), "r"(a[2]), "r"(a[3]), "r"(b0), "r"(b1));
}

__device__ __forceinline__ void ldsm_x4(uint32_t* r, uint32_t saddr) {
    asm volatile(
        "ldmatrix.sync.aligned.m8n8.x4.shared.b16 {%0,%1,%2,%3}, [%4];"
        : "=r"(r[0]), "=r"(r[1]), "=r"(r[2]), "=r"(r[3]) : "r"(saddr));
}

__device__ __forceinline__ uint32_t smem_u32(const void* p) {
    return (uint32_t)__cvta_generic_to_shared(p);
}

#define CP_ASYNC16(dst, src) \
    asm volatile("cp.async.cg.shared.global [%0], [%1], 16;" \
                 :: "r"(dst), "l"(src) : "memory")
#define CP_COMMIT() asm volatile("cp.async.commit_group;" ::: "memory")
#define CP_WAIT(n)  asm volatile("cp.async.wait_group %0;" :: "n"(n) : "memory")

// ============== cp.async 3-buffer tf32 batched GEMM ========================
// C[r] = A @ Bt[r]^T;  A raw fp32 (tf32-rounded in registers), Bt pre-rounded
// + pre-transposed. blockIdx.x = relation, blockIdx.y = M tile.
template<int BN, int Kdim>
__global__ __launch_bounds__(256)
void rgemm_cp(const float* __restrict__ A, const float* __restrict__ Bt,
              float* __restrict__ C) {
    constexpr int BM = 128, BK = 32, PAD = 36;
    constexpr int NCH = Kdim / BK;
    constexpr int WN = BN / 2, NT = WN / 8, NP = NT / 2;
    constexpr int ASTR = BM * PAD;
    constexpr int BSTR = BN * PAD;

    extern __shared__ __align__(16) float sm[];
    float* Asm = sm;                        // [3][BM][PAD]
    float* Bsm = sm + 3 * ASTR;             // [3][BN][PAD]

    const int r   = blockIdx.x;
    const int m0  = blockIdx.y * BM;
    const int tid = threadIdx.x;
    const int lane = tid & 31, wid = tid >> 5;
    const int mi = wid & 3, ni = wid >> 2;
    const int g = lane >> 2, t = lane & 3;

    const float* Ab = A + (size_t)m0 * Kdim;
    const float* Bb = Bt + (size_t)r * BN * Kdim;
    float*       Cr = C + (size_t)r * N_NODES * BN + (size_t)m0 * BN;

    const int j8 = lane >> 3, i8 = lane & 7;
    uint32_t aAddr[2];
#pragma unroll
    for (int mt = 0; mt < 2; mt++) {
        int row = mi * 32 + mt * 16 + (j8 & 1) * 8 + i8;
        aAddr[mt] = smem_u32(&Asm[row * PAD]) + (j8 >> 1) * 16;
    }
    uint32_t bAddr[NP];
#pragma unroll
    for (int p = 0; p < NP; p++) {
        int nrow = ni * WN + p * 16 + (j8 >> 1) * 8 + i8;
        bAddr[p] = smem_u32(&Bsm[nrow * PAD]) + (j8 & 1) * 16;
    }

    auto load_stage = [&](int c, int s) {
        float* Ad = Asm + s * ASTR;
#pragma unroll
        for (int i = 0; i < 4; i++) {
            int idx = i * 256 + tid;
            int row = idx >> 3, ch = (idx & 7) * 4;
            CP_ASYNC16(smem_u32(Ad + row * PAD + ch),
                       Ab + (size_t)row * Kdim + c * BK + ch);
        }
        float* Bd = Bsm + s * BSTR;
#pragma unroll
        for (int i = 0; i < BN / 32; i++) {
            int idx = i * 256 + tid;
            int row = idx >> 3, ch = (idx & 7) * 4;
            CP_ASYNC16(smem_u32(Bd + row * PAD + ch),
                       Bb + (size_t)row * Kdim + c * BK + ch);
        }
        CP_COMMIT();
    };

    float acc[2][NT][4];
#pragma unroll
    for (int mt = 0; mt < 2; mt++)
#pragma unroll
        for (int nt = 0; nt < NT; nt++)
#pragma unroll
            for (int q = 0; q < 4; q++) acc[mt][nt][q] = 0.f;

    load_stage(0, 0);
    load_stage(1, 1);

    for (int c = 0; c < NCH; c++) {
        const int s = c % 3;
        CP_WAIT(1);
        __syncthreads();
        if (c + 2 < NCH) load_stage(c + 2, (c + 2) % 3);
        else CP_COMMIT();

        const uint32_t ao = (uint32_t)s * ASTR * 4, bo = (uint32_t)s * BSTR * 4;
#pragma unroll
        for (int kk = 0; kk < 4; kk++) {
            uint32_t a[2][4];
            ldsm_x4(a[0], aAddr[0] + ao + kk * 32);
            ldsm_x4(a[1], aAddr[1] + ao + kk * 32);
#pragma unroll
            for (int mt = 0; mt < 2; mt++)
#pragma unroll
                for (int q = 0; q < 4; q++)
                    a[mt][q] = __float_as_uint(to_tf32(__uint_as_float(a[mt][q])));
#pragma unroll
            for (int p = 0; p < NP; p++) {
                uint32_t b[4];
                ldsm_x4(b, bAddr[p] + bo + kk * 32);
#pragma unroll
                for (int mt = 0; mt < 2; mt++) {
                    mma_tf32(acc[mt][2 * p],     a[mt], b[0], b[1]);
                    mma_tf32(acc[mt][2 * p + 1], a[mt], b[2], b[3]);
                }
            }
        }
    }

#pragma unroll
    for (int mt = 0; mt < 2; mt++) {
        int row = mi * 32 + mt * 16 + g;
#pragma unroll
        for (int nt = 0; nt < NT; nt++) {
            int col = ni * WN + nt * 8 + t * 2;
            *(float2*)&Cr[(size_t)row * BN + col] =
                make_float2(acc[mt][nt][0], acc[mt][nt][1]);
            *(float2*)&Cr[(size_t)(row + 8) * BN + col] =
                make_float2(acc[mt][nt][2], acc[mt][nt][3]);
        }
    }
}

// W[r][k][n] -> Wt[r][n][k], tf32-rounded
template<int K, int N>
__global__ void transpose_w(const float* __restrict__ W,
                            float* __restrict__ Wt) {
    int r = blockIdx.y;
    int idx = blockIdx.x * 256 + threadIdx.x;
    if (idx >= K * N) return;
    int k = idx / N, n = idx % N;
    Wt[((size_t)r * N + n) * K + k] = to_tf32(W[((size_t)r * K + k) * N + n]);
}

// ================= CSR build (by dst) =======================================
__global__ void csr_zero() {
    int i = blockIdx.x * 256 + threadIdx.x;
    if (i < N_NODES) { g_deg[i] = 0; g_fil[i] = 0; }
}

__global__ void csr_count(const int* __restrict__ eidx) {
    int e = blockIdx.x * 256 + threadIdx.x;
    if (e < N_EDGES) atomicAdd(&g_deg[eidx[N_EDGES + e]], 1);
}

// N_NODES = 400 * 256 exactly
__global__ void scan_blocks() {
    __shared__ int s[256];
    int i = blockIdx.x * 256 + threadIdx.x;
    int v = g_deg[i];
    s[threadIdx.x] = v; __syncthreads();
    for (int d = 1; d < 256; d <<= 1) {
        int x = (threadIdx.x >= d) ? s[threadIdx.x - d] : 0;
        __syncthreads();
        s[threadIdx.x] += x;
        __syncthreads();
    }
    g_off[i] = s[threadIdx.x] - v;                 // exclusive within block
    if (threadIdx.x == 255) g_bsum[blockIdx.x] = s[255];
}

__global__ void scan_tops() {
    __shared__ int s[512];
    int t = threadIdx.x;
    int v = (t < 400) ? g_bsum[t] : 0;
    s[t] = v; __syncthreads();
    for (int d = 1; d < 512; d <<= 1) {
        int x = (t >= d) ? s[t - d] : 0;
        __syncthreads();
        s[t] += x;
        __syncthreads();
    }
    if (t < 400) g_bsum[t] = s[t] - v;             // exclusive block base
    if (t == 0) g_off[N_NODES] = N_EDGES;
}

__global__ void scan_add() {
    int i = blockIdx.x * 256 + threadIdx.x;
    g_off[i] += g_bsum[blockIdx.x];
}

__global__ void csr_fill(const int* __restrict__ eidx,
                         const float* __restrict__ ew,
                         const int* __restrict__ et) {
    int e = blockIdx.x * 256 + threadIdx.x;
    if (e >= N_EDGES) return;
    int src = eidx[e], dst = eidx[N_EDGES + e], t = et[e];
    int pos = g_off[dst] + atomicAdd(&g_fil[dst], 1);
    g_es[pos]  = (uint32_t)src | ((uint32_t)t << 20);
    g_ewb[pos] = ew[e];
}

// ============ CSR gather-aggregate: h[n] = relu(bias + sum_e w*xw[t,src]) ===
// D/4 lanes per node; each lane owns 4 feats (coalesced float4 gathers).
template<int D>
__global__ void agg_csr(const float* __restrict__ xw,
                        const float* __restrict__ bias,
                        float* __restrict__ hout) {
    constexpr int L = D / 4;
    int gt = blockIdx.x * blockDim.x + threadIdx.x;
    int node = gt / L;
    int sub  = gt % L;
    if (node >= N_NODES) return;
    int beg = g_off[node], end = g_off[node + 1];

    float ax = 0.f, ay = 0.f, az = 0.f, aw = 0.f;
    for (int j = beg; j < end; j++) {
        uint32_t es = g_es[j];
        float    w  = g_ewb[j];
        int src = es & 0xFFFFF;
        int t   = es >> 20;
        float4 v = *(const float4*)&xw[((size_t)t * N_NODES + src) * D + sub * 4];
        ax += v.x * w; ay += v.y * w; az += v.z * w; aw += v.w * w;
    }
    float4 b = *(const float4*)&bias[sub * 4];
    ax = fmaxf(ax + b.x, 0.f); ay = fmaxf(ay + b.y, 0.f);
    az = fmaxf(az + b.z, 0.f); aw = fmaxf(aw + b.w, 0.f);
    *(float4*)&hout[(size_t)node * D + sub * 4] = make_float4(ax, ay, az, aw);
}

// layer 3: scalar per node; lane-per-edge + warp reduce (no relu on output)
__global__ void agg_out(const float* __restrict__ xw3,
                        const float* __restrict__ b3,
                        float* __restrict__ out) {
    int node = (blockIdx.x * blockDim.x + threadIdx.x) >> 5;
    int lane = threadIdx.x & 31;
    if (node >= N_NODES) return;
    int beg = g_off[node], end = g_off[node + 1];
    float s = 0.f;
    for (int j = beg + lane; j < end; j += 32) {
        uint32_t es = g_es[j];
        s += xw3[(size_t)(es >> 20) * N_NODES + (es & 0xFFFFF)] * g_ewb[j];
    }
#pragma unroll
    for (int o = 16; o; o >>= 1) s += __shfl_down_sync(0xffffffff, s, o);
    if (lane == 0) out[node] = s + b3[0];
}

// ---------------- layer-3 transform: xw3[r,n] = h2[n] . W3[r] (h2 relu'd) --
__global__ void gemm3_kernel(const float* __restrict__ h2,
                             const float* __restrict__ W3,
                             float* __restrict__ xw3) {
    __shared__ float w[N_REL][D2];
    for (int i = threadIdx.x; i < N_REL * D2; i += blockDim.x)
        w[i / D2][i % D2] = W3[i];
    __syncthreads();

    int n = blockIdx.x * blockDim.x + threadIdx.x;
    if (n >= N_NODES) return;

    float acc[N_REL];
#pragma unroll
    for (int r = 0; r < N_REL; r++) acc[r] = 0.f;

    const float4* hp = (const float4*)&h2[(size_t)n * D2];
#pragma unroll
    for (int k4 = 0; k4 < D2 / 4; k4++) {
        float4 v = hp[k4];
#pragma unroll
        for (int r = 0; r < N_REL; r++) {
            acc[r] += v.x * w[r][k4 * 4 + 0];
            acc[r] += v.y * w[r][k4 * 4 + 1];
            acc[r] += v.z * w[r][k4 * 4 + 2];
            acc[r] += v.w * w[r][k4 * 4 + 3];
        }
    }
#pragma unroll
    for (int r = 0; r < N_REL; r++)
        xw3[(size_t)r * N_NODES + n] = acc[r];
}

// ---------------- launcher --------------------------------------------------
extern "C" void kernel_launch(void* const* d_in, const int* in_sizes, int n_in,
                              void* d_out, int out_size) {
    const float* b_z  = (const float*)d_in[0];
    const int*   eidx = (const int*)d_in[1];
    const float* ew   = (const float*)d_in[2];
    const int*   et   = (const int*)d_in[3];
    const float* W1   = (const float*)d_in[4];
    const float* b1   = (const float*)d_in[5];
    const float* W2   = (const float*)d_in[6];
    const float* b2   = (const float*)d_in[7];
    const float* W3   = (const float*)d_in[8];
    const float* b3   = (const float*)d_in[9];
    float*       out  = (float*)d_out;

    void* p;
    float *xw1, *h1, *xw2, *h2, *xw3, *w1t, *w2t;
    cudaGetSymbolAddress(&p, g_xw1); xw1 = (float*)p;
    cudaGetSymbolAddress(&p, g_h1 ); h1  = (float*)p;
    cudaGetSymbolAddress(&p, g_xw2); xw2 = (float*)p;
    cudaGetSymbolAddress(&p, g_h2 ); h2  = (float*)p;
    cudaGetSymbolAddress(&p, g_xw3); xw3 = (float*)p;
    cudaGetSymbolAddress(&p, g_w1t); w1t = (float*)p;
    cudaGetSymbolAddress(&p, g_w2t); w2t = (float*)p;

    const int smem1 = 3 * (128 + 128) * 36 * 4;  // 110592
    const int smem2 = 3 * (128 + 64) * 36 * 4;   // 82944
    cudaFuncSetAttribute(rgemm_cp<128, 256>,
                         cudaFuncAttributeMaxDynamicSharedMemorySize, smem1);
    cudaFuncSetAttribute(rgemm_cp<64, 128>,
                         cudaFuncAttributeMaxDynamicSharedMemorySize, smem2);

    // ---- CSR build (by dst) + weight prep ----
    csr_zero<<<400, 256>>>();
    csr_count<<<N_EDGES / 256, 256>>>(eidx);
    scan_blocks<<<400, 256>>>();
    scan_tops<<<1, 512>>>();
    scan_add<<<400, 256>>>();
    csr_fill<<<N_EDGES / 256, 256>>>(eidx, ew, et);
    transpose_w<D0, D1><<<dim3((D0 * D1 + 255) / 256, N_REL), 256>>>(W1, w1t);
    transpose_w<D1, D2><<<dim3((D1 * D2 + 255) / 256, N_REL), 256>>>(W2, w2t);

    // ---- layer 1: xw1[r] = b_z @ w1t[r]^T; h1 = relu(b1 + aggregate) ----
    rgemm_cp<128, 256>
        <<<dim3(N_REL, N_NODES / 128), 256, smem1>>>(b_z, w1t, xw1);
    agg_csr<D1><<<N_NODES * (D1 / 4) / 256, 256>>>(xw1, b1, h1);

    // ---- layer 2: xw2[r] = h1 @ w2t[r]^T; h2 = relu(b2 + aggregate) ----
    rgemm_cp<64, 128>
        <<<dim3(N_REL, N_NODES / 128), 256, smem2>>>(h1, w2t, xw2);
    agg_csr<D2><<<N_NODES * (D2 / 4) / 256, 256>>>(xw2, b2, h2);

    // ---- layer 3: xw3[r,n] = h2[n] . W3[r]; out = b3 + aggregate ----
    gemm3_kernel<<<(N_NODES + 255) / 256, 256>>>(h2, W3, xw3);
    agg_out<<<N_NODES * 32 / 256, 256>>>(xw3, b3, out);
}

// round 14
// speedup vs baseline: 3.6356x; 1.1028x over previous
#include <cuda_runtime.h>
#include <cuda_fp16.h>
#include <cstdint>
#include <cstddef>

#define N_NODES 102400
#define N_EDGES 1638400
#define N_REL   8
#define D0      256
#define D1      128
#define D2      64

// ---------------- scratch (device globals; no allocation allowed) ----------
__device__ __align__(16) uint32_t g_xw1[(size_t)N_REL * N_NODES * D1 / 2]; // 210 MB fp16
__device__ __align__(16) float    g_h1 [(size_t)N_NODES * D1];             // 52 MB (relu'd)
__device__ __align__(16) uint32_t g_xw2[(size_t)N_REL * N_NODES * D2 / 2]; // 105 MB fp16
__device__ __align__(16) float    g_h2 [(size_t)N_NODES * D2];             // 26 MB (relu'd)
__device__ __align__(16) float    g_xw3[(size_t)N_REL * N_NODES];          // 3.3 MB
__device__ __align__(16) float    g_w1t[(size_t)N_REL * D1 * D0];          // 1 MB [r][n][k]
__device__ __align__(16) float    g_w2t[(size_t)N_REL * D2 * D1];          // 0.25 MB

// CSR-by-dst edge structure
__device__ int      g_deg[N_NODES];
__device__ int      g_fil[N_NODES];
__device__ int      g_off[N_NODES + 1];
__device__ int      g_bsum[400];
__device__ uint32_t g_es [N_EDGES];   // src | (t << 20)
__device__ float    g_ewb[N_EDGES];

__device__ __forceinline__ float to_tf32(float x) {
    float y;
    asm("cvt.rna.tf32.f32 %0, %1;" : "=f"(y) : "f"(x));
    return y;
}

__device__ __forceinline__ uint32_t pack_f16x2(float lo, float hi) {
    uint32_t r;
    asm("cvt.rn.f16x2.f32 %0, %1, %2;" : "=r"(r) : "f"(hi), "f"(lo));
    return r;
}

__device__ __forceinline__ float2 unpack_f16x2(uint32_t u) {
    __half2 h = *reinterpret_cast<__half2*>(&u);
    return __half22float2(h);
}

__device__ __forceinline__ void mma_tf32(float* c, const uint32_t* a,
                                         uint32_t b0, uint32_t b1) {
    asm volatile(
        "mma.sync.aligned.m16n8k8.row.col.f32.tf32.tf32.f32 "
        "{%0,%1,%2,%3}, {%4,%5,%6,%7}, {%8,%9}, {%0,%1,%2,%3};"
        : "+f"(c[0]), "+f"(c[1]), "+f"(c[2]), "+f"(c[3])
        : "r"(a[0]), "r"(a[1]), "r"(a[2]), "r"(a[3]), "r"(b0), "r"(b1));
}

__device__ __forceinline__ void ldsm_x4(uint32_t* r, uint32_t saddr) {
    asm volatile(
        "ldmatrix.sync.aligned.m8n8.x4.shared.b16 {%0,%1,%2,%3}, [%4];"
        : "=r"(r[0]), "=r"(r[1]), "=r"(r[2]), "=r"(r[3]) : "r"(saddr));
}

__device__ __forceinline__ uint32_t smem_u32(const void* p) {
    return (uint32_t)__cvta_generic_to_shared(p);
}

#define CP_ASYNC16(dst, src) \
    asm volatile("cp.async.cg.shared.global [%0], [%1], 16;" \
                 :: "r"(dst), "l"(src) : "memory")
#define CP_COMMIT() asm volatile("cp.async.commit_group;" ::: "memory")
#define CP_WAIT(n)  asm volatile("cp.async.wait_group %0;" :: "n"(n) : "memory")

// ============== cp.async 3-buffer tf32 batched GEMM, fp16 output ===========
// C[r] = A @ Bt[r]^T;  A raw fp32 (tf32-rounded in registers), Bt pre-rounded
// + pre-transposed. C stored as fp16 (packed f16x2 per uint32).
template<int BN, int Kdim>
__global__ __launch_bounds__(256)
void rgemm_cp(const float* __restrict__ A, const float* __restrict__ Bt,
              uint32_t* __restrict__ C) {
    constexpr int BM = 128, BK = 32, PAD = 36;
    constexpr int NCH = Kdim / BK;
    constexpr int WN = BN / 2, NT = WN / 8, NP = NT / 2;
    constexpr int ASTR = BM * PAD;
    constexpr int BSTR = BN * PAD;

    extern __shared__ __align__(16) float sm[];
    float* Asm = sm;                        // [3][BM][PAD]
    float* Bsm = sm + 3 * ASTR;             // [3][BN][PAD]

    const int r   = blockIdx.x;
    const int m0  = blockIdx.y * BM;
    const int tid = threadIdx.x;
    const int lane = tid & 31, wid = tid >> 5;
    const int mi = wid & 3, ni = wid >> 2;
    const int g = lane >> 2, t = lane & 3;

    const float* Ab = A + (size_t)m0 * Kdim;
    const float* Bb = Bt + (size_t)r * BN * Kdim;
    uint32_t*    Cr = C + (size_t)r * N_NODES * (BN / 2) + (size_t)m0 * (BN / 2);

    const int j8 = lane >> 3, i8 = lane & 7;
    uint32_t aAddr[2];
#pragma unroll
    for (int mt = 0; mt < 2; mt++) {
        int row = mi * 32 + mt * 16 + (j8 & 1) * 8 + i8;
        aAddr[mt] = smem_u32(&Asm[row * PAD]) + (j8 >> 1) * 16;
    }
    uint32_t bAddr[NP];
#pragma unroll
    for (int p = 0; p < NP; p++) {
        int nrow = ni * WN + p * 16 + (j8 >> 1) * 8 + i8;
        bAddr[p] = smem_u32(&Bsm[nrow * PAD]) + (j8 & 1) * 16;
    }

    auto load_stage = [&](int c, int s) {
        float* Ad = Asm + s * ASTR;
#pragma unroll
        for (int i = 0; i < 4; i++) {
            int idx = i * 256 + tid;
            int row = idx >> 3, ch = (idx & 7) * 4;
            CP_ASYNC16(smem_u32(Ad + row * PAD + ch),
                       Ab + (size_t)row * Kdim + c * BK + ch);
        }
        float* Bd = Bsm + s * BSTR;
#pragma unroll
        for (int i = 0; i < BN / 32; i++) {
            int idx = i * 256 + tid;
            int row = idx >> 3, ch = (idx & 7) * 4;
            CP_ASYNC16(smem_u32(Bd + row * PAD + ch),
                       Bb + (size_t)row * Kdim + c * BK + ch);
        }
        CP_COMMIT();
    };

    float acc[2][NT][4];
#pragma unroll
    for (int mt = 0; mt < 2; mt++)
#pragma unroll
        for (int nt = 0; nt < NT; nt++)
#pragma unroll
            for (int q = 0; q < 4; q++) acc[mt][nt][q] = 0.f;

    load_stage(0, 0);
    load_stage(1, 1);

    for (int c = 0; c < NCH; c++) {
        const int s = c % 3;
        CP_WAIT(1);
        __syncthreads();
        if (c + 2 < NCH) load_stage(c + 2, (c + 2) % 3);
        else CP_COMMIT();

        const uint32_t ao = (uint32_t)s * ASTR * 4, bo = (uint32_t)s * BSTR * 4;
#pragma unroll
        for (int kk = 0; kk < 4; kk++) {
            uint32_t a[2][4];
            ldsm_x4(a[0], aAddr[0] + ao + kk * 32);
            ldsm_x4(a[1], aAddr[1] + ao + kk * 32);
#pragma unroll
            for (int mt = 0; mt < 2; mt++)
#pragma unroll
                for (int q = 0; q < 4; q++)
                    a[mt][q] = __float_as_uint(to_tf32(__uint_as_float(a[mt][q])));
#pragma unroll
            for (int p = 0; p < NP; p++) {
                uint32_t b[4];
                ldsm_x4(b, bAddr[p] + bo + kk * 32);
#pragma unroll
                for (int mt = 0; mt < 2; mt++) {
                    mma_tf32(acc[mt][2 * p],     a[mt], b[0], b[1]);
                    mma_tf32(acc[mt][2 * p + 1], a[mt], b[2], b[3]);
                }
            }
        }
    }

    // ---- epilogue: pack adjacent cols (2t, 2t+1) as f16x2, store u32 ----
#pragma unroll
    for (int mt = 0; mt < 2; mt++) {
        int row = mi * 32 + mt * 16 + g;
#pragma unroll
        for (int nt = 0; nt < NT; nt++) {
            int col2 = (ni * WN + nt * 8) / 2 + t;
            Cr[(size_t)row * (BN / 2) + col2] =
                pack_f16x2(acc[mt][nt][0], acc[mt][nt][1]);
            Cr[(size_t)(row + 8) * (BN / 2) + col2] =
                pack_f16x2(acc[mt][nt][2], acc[mt][nt][3]);
        }
    }
}

// W[r][k][n] -> Wt[r][n][k], tf32-rounded
template<int K, int N>
__global__ void transpose_w(const float* __restrict__ W,
                            float* __restrict__ Wt) {
    int r = blockIdx.y;
    int idx = blockIdx.x * 256 + threadIdx.x;
    if (idx >= K * N) return;
    int k = idx / N, n = idx % N;
    Wt[((size_t)r * N + n) * K + k] = to_tf32(W[((size_t)r * K + k) * N + n]);
}

// ================= CSR build (by dst) =======================================
__global__ void csr_zero() {
    int i = blockIdx.x * 256 + threadIdx.x;
    if (i < N_NODES) { g_deg[i] = 0; g_fil[i] = 0; }
}

__global__ void csr_count(const int* __restrict__ eidx) {
    int e = blockIdx.x * 256 + threadIdx.x;
    if (e < N_EDGES) atomicAdd(&g_deg[eidx[N_EDGES + e]], 1);
}

__global__ void scan_blocks() {
    __shared__ int s[256];
    int i = blockIdx.x * 256 + threadIdx.x;
    int v = g_deg[i];
    s[threadIdx.x] = v; __syncthreads();
    for (int d = 1; d < 256; d <<= 1) {
        int x = (threadIdx.x >= d) ? s[threadIdx.x - d] : 0;
        __syncthreads();
        s[threadIdx.x] += x;
        __syncthreads();
    }
    g_off[i] = s[threadIdx.x] - v;
    if (threadIdx.x == 255) g_bsum[blockIdx.x] = s[255];
}

__global__ void scan_tops() {
    __shared__ int s[512];
    int t = threadIdx.x;
    int v = (t < 400) ? g_bsum[t] : 0;
    s[t] = v; __syncthreads();
    for (int d = 1; d < 512; d <<= 1) {
        int x = (t >= d) ? s[t - d] : 0;
        __syncthreads();
        s[t] += x;
        __syncthreads();
    }
    if (t < 400) g_bsum[t] = s[t] - v;
    if (t == 0) g_off[N_NODES] = N_EDGES;
}

__global__ void scan_add() {
    int i = blockIdx.x * 256 + threadIdx.x;
    g_off[i] += g_bsum[blockIdx.x];
}

__global__ void csr_fill(const int* __restrict__ eidx,
                         const float* __restrict__ ew,
                         const int* __restrict__ et) {
    int e = blockIdx.x * 256 + threadIdx.x;
    if (e >= N_EDGES) return;
    int src = eidx[e], dst = eidx[N_EDGES + e], t = et[e];
    int pos = g_off[dst] + atomicAdd(&g_fil[dst], 1);
    g_es[pos]  = (uint32_t)src | ((uint32_t)t << 20);
    g_ewb[pos] = ew[e];
}

// ===== CSR gather-aggregate (fp16 xw): h[n] = relu(bias + sum w*xw[t,src]) =
// D/8 lanes per node; each lane owns 8 feats = one uint4 (4x f16x2).
template<int D>
__global__ void agg_csr(const uint32_t* __restrict__ xw,
                        const float* __restrict__ bias,
                        float* __restrict__ hout) {
    constexpr int L = D / 8;
    int gt = blockIdx.x * blockDim.x + threadIdx.x;
    int node = gt / L;
    int sub  = gt % L;
    if (node >= N_NODES) return;
    int beg = g_off[node], end = g_off[node + 1];

    float acc[8];
#pragma unroll
    for (int q = 0; q < 8; q++) acc[q] = 0.f;

    const uint4* xw4 = (const uint4*)xw;
    for (int j = beg; j < end; j++) {
        uint32_t es = g_es[j];
        float    w  = g_ewb[j];
        int src = es & 0xFFFFF;
        int t   = es >> 20;
        uint4 v = xw4[((size_t)t * N_NODES + src) * (D / 8) + sub];
        float2 f0 = unpack_f16x2(v.x), f1 = unpack_f16x2(v.y);
        float2 f2 = unpack_f16x2(v.z), f3 = unpack_f16x2(v.w);
        acc[0] += f0.x * w; acc[1] += f0.y * w;
        acc[2] += f1.x * w; acc[3] += f1.y * w;
        acc[4] += f2.x * w; acc[5] += f2.y * w;
        acc[6] += f3.x * w; acc[7] += f3.y * w;
    }
    float4 b0 = *(const float4*)&bias[sub * 8];
    float4 b1 = *(const float4*)&bias[sub * 8 + 4];
    float* hp = &hout[(size_t)node * D + sub * 8];
    *(float4*)hp = make_float4(
        fmaxf(acc[0] + b0.x, 0.f), fmaxf(acc[1] + b0.y, 0.f),
        fmaxf(acc[2] + b0.z, 0.f), fmaxf(acc[3] + b0.w, 0.f));
    *(float4*)(hp + 4) = make_float4(
        fmaxf(acc[4] + b1.x, 0.f), fmaxf(acc[5] + b1.y, 0.f),
        fmaxf(acc[6] + b1.z, 0.f), fmaxf(acc[7] + b1.w, 0.f));
}

// layer 3: lane-per-edge + warp reduce (no relu on output)
__global__ void agg_out(const float* __restrict__ xw3,
                        const float* __restrict__ b3,
                        float* __restrict__ out) {
    int node = (blockIdx.x * blockDim.x + threadIdx.x) >> 5;
    int lane = threadIdx.x & 31;
    if (node >= N_NODES) return;
    int beg = g_off[node], end = g_off[node + 1];
    float s = 0.f;
    for (int j = beg + lane; j < end; j += 32) {
        uint32_t es = g_es[j];
        s += xw3[(size_t)(es >> 20) * N_NODES + (es & 0xFFFFF)] * g_ewb[j];
    }
#pragma unroll
    for (int o = 16; o; o >>= 1) s += __shfl_down_sync(0xffffffff, s, o);
    if (lane == 0) out[node] = s + b3[0];
}

// ---------------- layer-3 transform: xw3[r,n] = h2[n] . W3[r] --------------
__global__ void gemm3_kernel(const float* __restrict__ h2,
                             const float* __restrict__ W3,
                             float* __restrict__ xw3) {
    __shared__ float w[N_REL][D2];
    for (int i = threadIdx.x; i < N_REL * D2; i += blockDim.x)
        w[i / D2][i % D2] = W3[i];
    __syncthreads();

    int n = blockIdx.x * blockDim.x + threadIdx.x;
    if (n >= N_NODES) return;

    float acc[N_REL];
#pragma unroll
    for (int r = 0; r < N_REL; r++) acc[r] = 0.f;

    const float4* hp = (const float4*)&h2[(size_t)n * D2];
#pragma unroll
    for (int k4 = 0; k4 < D2 / 4; k4++) {
        float4 v = hp[k4];
#pragma unroll
        for (int r = 0; r < N_REL; r++) {
            acc[r] += v.x * w[r][k4 * 4 + 0];
            acc[r] += v.y * w[r][k4 * 4 + 1];
            acc[r] += v.z * w[r][k4 * 4 + 2];
            acc[r] += v.w * w[r][k4 * 4 + 3];
        }
    }
#pragma unroll
    for (int r = 0; r < N_REL; r++)
        xw3[(size_t)r * N_NODES + n] = acc[r];
}

// ---------------- launcher --------------------------------------------------
extern "C" void kernel_launch(void* const* d_in, const int* in_sizes, int n_in,
                              void* d_out, int out_size) {
    const float* b_z  = (const float*)d_in[0];
    const int*   eidx = (const int*)d_in[1];
    const float* ew   = (const float*)d_in[2];
    const int*   et   = (const int*)d_in[3];
    const float* W1   = (const float*)d_in[4];
    const float* b1   = (const float*)d_in[5];
    const float* W2   = (const float*)d_in[6];
    const float* b2   = (const float*)d_in[7];
    const float* W3   = (const float*)d_in[8];
    const float* b3   = (const float*)d_in[9];
    float*       out  = (float*)d_out;

    void* p;
    uint32_t *xw1, *xw2;
    float *h1, *h2, *xw3, *w1t, *w2t;
    cudaGetSymbolAddress(&p, g_xw1); xw1 = (uint32_t*)p;
    cudaGetSymbolAddress(&p, g_h1 ); h1  = (float*)p;
    cudaGetSymbolAddress(&p, g_xw2); xw2 = (uint32_t*)p;
    cudaGetSymbolAddress(&p, g_h2 ); h2  = (float*)p;
    cudaGetSymbolAddress(&p, g_xw3); xw3 = (float*)p;
    cudaGetSymbolAddress(&p, g_w1t); w1t = (float*)p;
    cudaGetSymbolAddress(&p, g_w2t); w2t = (float*)p;

    const int smem1 = 3 * (128 + 128) * 36 * 4;  // 110592
    const int smem2 = 3 * (128 + 64) * 36 * 4;   // 82944
    cudaFuncSetAttribute(rgemm_cp<128, 256>,
                         cudaFuncAttributeMaxDynamicSharedMemorySize, smem1);
    cudaFuncSetAttribute(rgemm_cp<64, 128>,
                         cudaFuncAttributeMaxDynamicSharedMemorySize, smem2);

    // ---- CSR build (by dst) + weight prep ----
    csr_zero<<<400, 256>>>();
    csr_count<<<N_EDGES / 256, 256>>>(eidx);
    scan_blocks<<<400, 256>>>();
    scan_tops<<<1, 512>>>();
    scan_add<<<400, 256>>>();
    csr_fill<<<N_EDGES / 256, 256>>>(eidx, ew, et);
    transpose_w<D0, D1><<<dim3((D0 * D1 + 255) / 256, N_REL), 256>>>(W1, w1t);
    transpose_w<D1, D2><<<dim3((D1 * D2 + 255) / 256, N_REL), 256>>>(W2, w2t);

    // ---- layer 1: xw1[r] = b_z @ w1t[r]^T (fp16); h1 = relu(b1 + agg) ----
    rgemm_cp<128, 256>
        <<<dim3(N_REL, N_NODES / 128), 256, smem1>>>(b_z, w1t, xw1);
    agg_csr<D1><<<N_NODES * (D1 / 8) / 256, 256>>>(xw1, b1, h1);

    // ---- layer 2: xw2[r] = h1 @ w2t[r]^T (fp16); h2 = relu(b2 + agg) ----
    rgemm_cp<64, 128>
        <<<dim3(N_REL, N_NODES / 128), 256, smem2>>>(h1, w2t, xw2);
    agg_csr<D2><<<N_NODES * (D2 / 8) / 256, 256>>>(xw2, b2, h2);

    // ---- layer 3: xw3[r,n] = h2[n] . W3[r]; out = b3 + aggregate ----
    gemm3_kernel<<<(N_NODES + 255) / 256, 256>>>(h2, W3, xw3);
    agg_out<<<N_NODES * 32 / 256, 256>>>(xw3, b3, out);
}

// round 15
// speedup vs baseline: 4.6085x; 1.2676x over previous
#include <cuda_runtime.h>
#include <cuda_fp16.h>
#include <cstdint>
#include <cstddef>

#define N_NODES 102400
#define N_EDGES 1638400
#define N_REL   8
#define D0      256
#define D1      128
#define D2      64

// ---------------- scratch (device globals; no allocation allowed) ----------
__device__ __align__(16) __half   g_a1h[(size_t)N_NODES * D0];             // 52 MB fp16 b_z
__device__ __align__(16) uint32_t g_xw1[(size_t)N_REL * N_NODES * D1 / 2]; // 210 MB fp16
__device__ __align__(16) uint32_t g_h1 [(size_t)N_NODES * D1 / 2];         // 26 MB fp16
__device__ __align__(16) uint32_t g_xw2[(size_t)N_REL * N_NODES * D2 / 2]; // 105 MB fp16
__device__ __align__(16) uint32_t g_h2 [(size_t)N_NODES * D2 / 2];         // 13 MB fp16
__device__ __align__(16) float    g_xw3[(size_t)N_REL * N_NODES];          // 3.3 MB
__device__ __align__(16) __half   g_w1t[(size_t)N_REL * D1 * D0];          // 0.5 MB [r][n][k]
__device__ __align__(16) __half   g_w2t[(size_t)N_REL * D2 * D1];          // 0.13 MB

// CSR-by-dst edge structure
__device__ int      g_deg[N_NODES];
__device__ int      g_fil[N_NODES];
__device__ int      g_off[N_NODES + 1];
__device__ int      g_bsum[400];
__device__ uint32_t g_es [N_EDGES];   // src | (t << 20)
__device__ float    g_ewb[N_EDGES];

__device__ __forceinline__ uint32_t pack_f16x2(float lo, float hi) {
    uint32_t r;
    asm("cvt.rn.f16x2.f32 %0, %1, %2;" : "=r"(r) : "f"(hi), "f"(lo));
    return r;
}

__device__ __forceinline__ float2 unpack_f16x2(uint32_t u) {
    __half2 h = *reinterpret_cast<__half2*>(&u);
    return __half22float2(h);
}

__device__ __forceinline__ void mma_f16(float* c, const uint32_t* a,
                                        uint32_t b0, uint32_t b1) {
    asm volatile(
        "mma.sync.aligned.m16n8k16.row.col.f32.f16.f16.f32 "
        "{%0,%1,%2,%3}, {%4,%5,%6,%7}, {%8,%9}, {%0,%1,%2,%3};"
        : "+f"(c[0]), "+f"(c[1]), "+f"(c[2]), "+f"(c[3])
        : "r"(a[0]), "r"(a[1]), "r"(a[2]), "r"(a[3]), "r"(b0), "r"(b1));
}

__device__ __forceinline__ void ldsm_x4(uint32_t* r, uint32_t saddr) {
    asm volatile(
        "ldmatrix.sync.aligned.m8n8.x4.shared.b16 {%0,%1,%2,%3}, [%4];"
        : "=r"(r[0]), "=r"(r[1]), "=r"(r[2]), "=r"(r[3]) : "r"(saddr));
}

__device__ __forceinline__ uint32_t smem_u32(const void* p) {
    return (uint32_t)__cvta_generic_to_shared(p);
}

#define CP_ASYNC16(dst, src) \
    asm volatile("cp.async.cg.shared.global [%0], [%1], 16;" \
                 :: "r"(dst), "l"(src) : "memory")
#define CP_COMMIT() asm volatile("cp.async.commit_group;" ::: "memory")
#define CP_WAIT(n)  asm volatile("cp.async.wait_group %0;" :: "n"(n) : "memory")

// ============== cp.async 3-buffer fp16 batched GEMM (fp32 accum) ===========
// C[r] = A @ Bt[r]^T;  A:[N,Kdim] fp16, Bt:[R][BN][Kdim] fp16 (pre-transposed)
// mma m16n8k16. blockIdx.x = relation, blockIdx.y = M tile. 8 warps 4(M)x2(N).
// PAD2=40 halfs (80B rows): 16B-aligned cp.async; 8 LDSM row addrs cover all
// 32 banks exactly once (conflict-free).
template<int BN, int Kdim>
__global__ __launch_bounds__(256)
void rgemm_h(const __half* __restrict__ A, const __half* __restrict__ Bt,
             uint32_t* __restrict__ C) {
    constexpr int BM = 128, BK = 32, PAD2 = 40;
    constexpr int NCH = Kdim / BK;
    constexpr int WN = BN / 2, NT = WN / 8, NP = NT / 2;
    constexpr int ASTR = BM * PAD2;          // halfs per A stage
    constexpr int BSTR = BN * PAD2;

    extern __shared__ __align__(16) __half smh[];
    __half* Asm = smh;                       // [3][BM][PAD2]
    __half* Bsm = smh + 3 * ASTR;            // [3][BN][PAD2]

    const int r   = blockIdx.x;
    const int m0  = blockIdx.y * BM;
    const int tid = threadIdx.x;
    const int lane = tid & 31, wid = tid >> 5;
    const int mi = wid & 3, ni = wid >> 2;
    const int g = lane >> 2, t = lane & 3;

    const __half* Ab = A + (size_t)m0 * Kdim;
    const __half* Bb = Bt + (size_t)r * BN * Kdim;
    uint32_t*     Cr = C + (size_t)r * N_NODES * (BN / 2) + (size_t)m0 * (BN / 2);

    // ---- ldmatrix per-thread base addresses (stage 0) ----
    const int j8 = lane >> 3, i8 = lane & 7;
    // A x4: m0=(rows+0,k0) m1=(rows+8,k0) m2=(rows+0,k+8) m3=(rows+8,k+8)
    uint32_t aAddr[2];
#pragma unroll
    for (int mt = 0; mt < 2; mt++) {
        int row = mi * 32 + mt * 16 + (j8 & 1) * 8 + i8;
        aAddr[mt] = smem_u32(&Asm[row * PAD2]) + (j8 >> 1) * 16;
    }
    // B x4: m0=(n+0,k0) m1=(n+0,k+8) m2=(n+8,k0) m3=(n+8,k+8)
    uint32_t bAddr[NP];
#pragma unroll
    for (int p = 0; p < NP; p++) {
        int nrow = ni * WN + p * 16 + (j8 >> 1) * 8 + i8;
        bAddr[p] = smem_u32(&Bsm[nrow * PAD2]) + (j8 & 1) * 16;
    }

    // ---- tile loader: raw 16B cp.async (8 halfs per chunk) ----
    auto load_stage = [&](int c, int s) {
        __half* Ad = Asm + s * ASTR;
#pragma unroll
        for (int i = 0; i < 2; i++) {        // 128 rows x 4 chunks
            int idx = i * 256 + tid;
            int row = idx >> 2, ch = (idx & 3) * 8;
            CP_ASYNC16(smem_u32(Ad + row * PAD2 + ch),
                       Ab + (size_t)row * Kdim + c * BK + ch);
        }
        __half* Bd = Bsm + s * BSTR;
#pragma unroll
        for (int i = 0; i < BN / 64; i++) {  // BN rows x 4 chunks
            int idx = i * 256 + tid;
            int row = idx >> 2, ch = (idx & 3) * 8;
            CP_ASYNC16(smem_u32(Bd + row * PAD2 + ch),
                       Bb + (size_t)row * Kdim + c * BK + ch);
        }
        CP_COMMIT();
    };

    float acc[2][NT][4];
#pragma unroll
    for (int mt = 0; mt < 2; mt++)
#pragma unroll
        for (int nt = 0; nt < NT; nt++)
#pragma unroll
            for (int q = 0; q < 4; q++) acc[mt][nt][q] = 0.f;

    load_stage(0, 0);
    load_stage(1, 1);

    for (int c = 0; c < NCH; c++) {
        const int s = c % 3;
        CP_WAIT(1);
        __syncthreads();
        if (c + 2 < NCH) load_stage(c + 2, (c + 2) % 3);
        else CP_COMMIT();

        const uint32_t ao = (uint32_t)s * ASTR * 2, bo = (uint32_t)s * BSTR * 2;
#pragma unroll
        for (int kk = 0; kk < 2; kk++) {     // 2 x (K=16)
            uint32_t a[2][4];
            ldsm_x4(a[0], aAddr[0] + ao + kk * 32);
            ldsm_x4(a[1], aAddr[1] + ao + kk * 32);
#pragma unroll
            for (int p = 0; p < NP; p++) {
                uint32_t b[4];
                ldsm_x4(b, bAddr[p] + bo + kk * 32);
#pragma unroll
                for (int mt = 0; mt < 2; mt++) {
                    mma_f16(acc[mt][2 * p],     a[mt], b[0], b[1]);
                    mma_f16(acc[mt][2 * p + 1], a[mt], b[2], b[3]);
                }
            }
        }
    }

    // ---- epilogue: pack adjacent cols (2t, 2t+1) as f16x2, store u32 ----
#pragma unroll
    for (int mt = 0; mt < 2; mt++) {
        int row = mi * 32 + mt * 16 + g;
#pragma unroll
        for (int nt = 0; nt < NT; nt++) {
            int col2 = (ni * WN + nt * 8) / 2 + t;
            Cr[(size_t)row * (BN / 2) + col2] =
                pack_f16x2(acc[mt][nt][0], acc[mt][nt][1]);
            Cr[(size_t)(row + 8) * (BN / 2) + col2] =
                pack_f16x2(acc[mt][nt][2], acc[mt][nt][3]);
        }
    }
}

// ---------------- pre-pass: fp32 -> fp16 (b_z) ------------------------------
__global__ void f32_to_f16(const float* __restrict__ src,
                           uint32_t* __restrict__ dst, size_t n8) {
    size_t i = (size_t)blockIdx.x * blockDim.x + threadIdx.x;
    if (i >= n8) return;
    float4 v0 = *(const float4*)(src + i * 8);
    float4 v1 = *(const float4*)(src + i * 8 + 4);
    uint4 o;
    o.x = pack_f16x2(v0.x, v0.y);
    o.y = pack_f16x2(v0.z, v0.w);
    o.z = pack_f16x2(v1.x, v1.y);
    o.w = pack_f16x2(v1.z, v1.w);
    *(uint4*)(dst + i * 4) = o;
}

// W[r][k][n] -> Wt[r][n][k], fp16
template<int K, int N>
__global__ void transpose_w(const float* __restrict__ W,
                            __half* __restrict__ Wt) {
    int r = blockIdx.y;
    int idx = blockIdx.x * 256 + threadIdx.x;
    if (idx >= K * N) return;
    int k = idx / N, n = idx % N;
    Wt[((size_t)r * N + n) * K + k] = __float2half_rn(W[((size_t)r * K + k) * N + n]);
}

// ================= CSR build (by dst) =======================================
__global__ void csr_zero() {
    int i = blockIdx.x * 256 + threadIdx.x;
    if (i < N_NODES) { g_deg[i] = 0; g_fil[i] = 0; }
}

__global__ void csr_count(const int* __restrict__ eidx) {
    int e = blockIdx.x * 256 + threadIdx.x;
    if (e < N_EDGES) atomicAdd(&g_deg[eidx[N_EDGES + e]], 1);
}

__global__ void scan_blocks() {
    __shared__ int s[256];
    int i = blockIdx.x * 256 + threadIdx.x;
    int v = g_deg[i];
    s[threadIdx.x] = v; __syncthreads();
    for (int d = 1; d < 256; d <<= 1) {
        int x = (threadIdx.x >= d) ? s[threadIdx.x - d] : 0;
        __syncthreads();
        s[threadIdx.x] += x;
        __syncthreads();
    }
    g_off[i] = s[threadIdx.x] - v;
    if (threadIdx.x == 255) g_bsum[blockIdx.x] = s[255];
}

__global__ void scan_tops() {
    __shared__ int s[512];
    int t = threadIdx.x;
    int v = (t < 400) ? g_bsum[t] : 0;
    s[t] = v; __syncthreads();
    for (int d = 1; d < 512; d <<= 1) {
        int x = (t >= d) ? s[t - d] : 0;
        __syncthreads();
        s[t] += x;
        __syncthreads();
    }
    if (t < 400) g_bsum[t] = s[t] - v;
    if (t == 0) g_off[N_NODES] = N_EDGES;
}

__global__ void scan_add() {
    int i = blockIdx.x * 256 + threadIdx.x;
    g_off[i] += g_bsum[blockIdx.x];
}

__global__ void csr_fill(const int* __restrict__ eidx,
                         const float* __restrict__ ew,
                         const int* __restrict__ et) {
    int e = blockIdx.x * 256 + threadIdx.x;
    if (e >= N_EDGES) return;
    int src = eidx[e], dst = eidx[N_EDGES + e], t = et[e];
    int pos = g_off[dst] + atomicAdd(&g_fil[dst], 1);
    g_es[pos]  = (uint32_t)src | ((uint32_t)t << 20);
    g_ewb[pos] = ew[e];
}

// ===== CSR gather-aggregate (fp16 xw -> fp16 h) ============================
// D/8 lanes per node; each lane owns 8 feats = one uint4 (4x f16x2).
template<int D>
__global__ void agg_csr(const uint32_t* __restrict__ xw,
                        const float* __restrict__ bias,
                        uint32_t* __restrict__ hout) {
    constexpr int L = D / 8;
    int gt = blockIdx.x * blockDim.x + threadIdx.x;
    int node = gt / L;
    int sub  = gt % L;
    if (node >= N_NODES) return;
    int beg = g_off[node], end = g_off[node + 1];

    float acc[8];
#pragma unroll
    for (int q = 0; q < 8; q++) acc[q] = 0.f;

    const uint4* xw4 = (const uint4*)xw;
    for (int j = beg; j < end; j++) {
        uint32_t es = g_es[j];
        float    w  = g_ewb[j];
        int src = es & 0xFFFFF;
        int t   = es >> 20;
        uint4 v = xw4[((size_t)t * N_NODES + src) * (D / 8) + sub];
        float2 f0 = unpack_f16x2(v.x), f1 = unpack_f16x2(v.y);
        float2 f2 = unpack_f16x2(v.z), f3 = unpack_f16x2(v.w);
        acc[0] += f0.x * w; acc[1] += f0.y * w;
        acc[2] += f1.x * w; acc[3] += f1.y * w;
        acc[4] += f2.x * w; acc[5] += f2.y * w;
        acc[6] += f3.x * w; acc[7] += f3.y * w;
    }
    float4 b0 = *(const float4*)&bias[sub * 8];
    float4 b1 = *(const float4*)&bias[sub * 8 + 4];
    uint4 o;
    o.x = pack_f16x2(fmaxf(acc[0] + b0.x, 0.f), fmaxf(acc[1] + b0.y, 0.f));
    o.y = pack_f16x2(fmaxf(acc[2] + b0.z, 0.f), fmaxf(acc[3] + b0.w, 0.f));
    o.z = pack_f16x2(fmaxf(acc[4] + b1.x, 0.f), fmaxf(acc[5] + b1.y, 0.f));
    o.w = pack_f16x2(fmaxf(acc[6] + b1.z, 0.f), fmaxf(acc[7] + b1.w, 0.f));
    *(uint4*)&hout[(size_t)node * (D / 2) + sub * 4] = o;
}

// layer 3: lane-per-edge + warp reduce (no relu on output)
__global__ void agg_out(const float* __restrict__ xw3,
                        const float* __restrict__ b3,
                        float* __restrict__ out) {
    int node = (blockIdx.x * blockDim.x + threadIdx.x) >> 5;
    int lane = threadIdx.x & 31;
    if (node >= N_NODES) return;
    int beg = g_off[node], end = g_off[node + 1];
    float s = 0.f;
    for (int j = beg + lane; j < end; j += 32) {
        uint32_t es = g_es[j];
        s += xw3[(size_t)(es >> 20) * N_NODES + (es & 0xFFFFF)] * g_ewb[j];
    }
#pragma unroll
    for (int o = 16; o; o >>= 1) s += __shfl_down_sync(0xffffffff, s, o);
    if (lane == 0) out[node] = s + b3[0];
}

// ---------------- layer-3 transform: xw3[r,n] = h2[n] . W3[r] (h2 fp16) ----
__global__ void gemm3_kernel(const uint32_t* __restrict__ h2,
                             const float* __restrict__ W3,
                             float* __restrict__ xw3) {
    __shared__ float w[N_REL][D2];
    for (int i = threadIdx.x; i < N_REL * D2; i += blockDim.x)
        w[i / D2][i % D2] = W3[i];
    __syncthreads();

    int n = blockIdx.x * blockDim.x + threadIdx.x;
    if (n >= N_NODES) return;

    float acc[N_REL];
#pragma unroll
    for (int r = 0; r < N_REL; r++) acc[r] = 0.f;

    const uint32_t* hp = &h2[(size_t)n * (D2 / 2)];
#pragma unroll
    for (int k2 = 0; k2 < D2 / 2; k2++) {
        float2 f = unpack_f16x2(hp[k2]);
#pragma unroll
        for (int r = 0; r < N_REL; r++) {
            acc[r] += f.x * w[r][k2 * 2 + 0];
            acc[r] += f.y * w[r][k2 * 2 + 1];
        }
    }
#pragma unroll
    for (int r = 0; r < N_REL; r++)
        xw3[(size_t)r * N_NODES + n] = acc[r];
}

// ---------------- launcher --------------------------------------------------
extern "C" void kernel_launch(void* const* d_in, const int* in_sizes, int n_in,
                              void* d_out, int out_size) {
    const float* b_z  = (const float*)d_in[0];
    const int*   eidx = (const int*)d_in[1];
    const float* ew   = (const float*)d_in[2];
    const int*   et   = (const int*)d_in[3];
    const float* W1   = (const float*)d_in[4];
    const float* b1   = (const float*)d_in[5];
    const float* W2   = (const float*)d_in[6];
    const float* b2   = (const float*)d_in[7];
    const float* W3   = (const float*)d_in[8];
    const float* b3   = (const float*)d_in[9];
    float*       out  = (float*)d_out;

    void* p;
    __half *a1h, *w1t, *w2t;
    uint32_t *xw1, *xw2, *h1, *h2;
    float *xw3;
    cudaGetSymbolAddress(&p, g_a1h); a1h = (__half*)p;
    cudaGetSymbolAddress(&p, g_xw1); xw1 = (uint32_t*)p;
    cudaGetSymbolAddress(&p, g_h1 ); h1  = (uint32_t*)p;
    cudaGetSymbolAddress(&p, g_xw2); xw2 = (uint32_t*)p;
    cudaGetSymbolAddress(&p, g_h2 ); h2  = (uint32_t*)p;
    cudaGetSymbolAddress(&p, g_xw3); xw3 = (float*)p;
    cudaGetSymbolAddress(&p, g_w1t); w1t = (__half*)p;
    cudaGetSymbolAddress(&p, g_w2t); w2t = (__half*)p;

    const int smem1 = 3 * (128 + 128) * 40 * 2;  // 61440
    const int smem2 = 3 * (128 + 64) * 40 * 2;   // 46080
    cudaFuncSetAttribute(rgemm_h<128, 256>,
                         cudaFuncAttributeMaxDynamicSharedMemorySize, smem1);
    cudaFuncSetAttribute(rgemm_h<64, 128>,
                         cudaFuncAttributeMaxDynamicSharedMemorySize, smem2);

    // ---- CSR build (by dst) + input/weight conversion ----
    csr_zero<<<400, 256>>>();
    csr_count<<<N_EDGES / 256, 256>>>(eidx);
    scan_blocks<<<400, 256>>>();
    scan_tops<<<1, 512>>>();
    scan_add<<<400, 256>>>();
    csr_fill<<<N_EDGES / 256, 256>>>(eidx, ew, et);
    f32_to_f16<<<(int)(((size_t)N_NODES * D0 / 8 + 255) / 256), 256>>>(
        b_z, (uint32_t*)a1h, (size_t)N_NODES * D0 / 8);
    transpose_w<D0, D1><<<dim3((D0 * D1 + 255) / 256, N_REL), 256>>>(W1, w1t);
    transpose_w<D1, D2><<<dim3((D1 * D2 + 255) / 256, N_REL), 256>>>(W2, w2t);

    // ---- layer 1: xw1[r] = a1h @ w1t[r]^T (fp16); h1 = relu(b1 + agg) ----
    rgemm_h<128, 256>
        <<<dim3(N_REL, N_NODES / 128), 256, smem1>>>(a1h, w1t, xw1);
    agg_csr<D1><<<N_NODES * (D1 / 8) / 256, 256>>>(xw1, b1, h1);

    // ---- layer 2: xw2[r] = h1 @ w2t[r]^T (fp16); h2 = relu(b2 + agg) ----
    rgemm_h<64, 128>
        <<<dim3(N_REL, N_NODES / 128), 256, smem2>>>((const __half*)h1, w2t, xw2);
    agg_csr<D2><<<N_NODES * (D2 / 8) / 256, 256>>>(xw2, b2, h2);

    // ---- layer 3: xw3[r,n] = h2[n] . W3[r]; out = b3 + aggregate ----
    gemm3_kernel<<<(N_NODES + 255) / 256, 256>>>(h2, W3, xw3);
    agg_out<<<N_NODES * 32 / 256, 256>>>(xw3, b3, out);
}

// round 16
// speedup vs baseline: 4.8749x; 1.0578x over previous
#include <cuda_runtime.h>
#include <cuda_fp16.h>
#include <cstdint>
#include <cstddef>

#define N_NODES 102400
#define N_EDGES 1638400
#define N_REL   8
#define D0      256
#define D1      128
#define D2      64

// ---------------- scratch (device globals; no allocation allowed) ----------
__device__ __align__(16) __half   g_a1h[(size_t)N_NODES * D0];             // 52 MB fp16 b_z
__device__ __align__(16) uint32_t g_xw1[(size_t)N_REL * N_NODES * D1 / 2]; // 210 MB fp16
__device__ __align__(16) uint32_t g_h1 [(size_t)N_NODES * D1 / 2];         // 26 MB fp16
__device__ __align__(16) uint32_t g_xw2[(size_t)N_REL * N_NODES * D2 / 2]; // 105 MB fp16
__device__ __align__(16) uint32_t g_h2 [(size_t)N_NODES * D2 / 2];         // 13 MB fp16
__device__ __align__(16) float    g_xw3[(size_t)N_REL * N_NODES];          // 3.3 MB
__device__ __align__(16) __half   g_w1t[(size_t)N_REL * D1 * D0];          // 0.5 MB [r][n][k]
__device__ __align__(16) __half   g_w2t[(size_t)N_REL * D2 * D1];          // 0.13 MB

// CSR-by-dst edge structure (packed: .x = src | t<<20, .y = weight bits)
__device__ int   g_deg[N_NODES];
__device__ int   g_fil[N_NODES];
__device__ int   g_off[N_NODES + 1];
__device__ int   g_bsum[400];
__device__ __align__(16) uint2 g_epk[N_EDGES];   // 12.6 MB

__device__ __forceinline__ uint32_t pack_f16x2(float lo, float hi) {
    uint32_t r;
    asm("cvt.rn.f16x2.f32 %0, %1, %2;" : "=r"(r) : "f"(hi), "f"(lo));
    return r;
}

__device__ __forceinline__ float2 unpack_f16x2(uint32_t u) {
    __half2 h = *reinterpret_cast<__half2*>(&u);
    return __half22float2(h);
}

__device__ __forceinline__ void mma_f16(float* c, const uint32_t* a,
                                        uint32_t b0, uint32_t b1) {
    asm volatile(
        "mma.sync.aligned.m16n8k16.row.col.f32.f16.f16.f32 "
        "{%0,%1,%2,%3}, {%4,%5,%6,%7}, {%8,%9}, {%0,%1,%2,%3};"
        : "+f"(c[0]), "+f"(c[1]), "+f"(c[2]), "+f"(c[3])
        : "r"(a[0]), "r"(a[1]), "r"(a[2]), "r"(a[3]), "r"(b0), "r"(b1));
}

__device__ __forceinline__ void ldsm_x4(uint32_t* r, uint32_t saddr) {
    asm volatile(
        "ldmatrix.sync.aligned.m8n8.x4.shared.b16 {%0,%1,%2,%3}, [%4];"
        : "=r"(r[0]), "=r"(r[1]), "=r"(r[2]), "=r"(r[3]) : "r"(saddr));
}

__device__ __forceinline__ uint32_t smem_u32(const void* p) {
    return (uint32_t)__cvta_generic_to_shared(p);
}

#define CP_ASYNC16(dst, src) \
    asm volatile("cp.async.cg.shared.global [%0], [%1], 16;" \
                 :: "r"(dst), "l"(src) : "memory")
#define CP_COMMIT() asm volatile("cp.async.commit_group;" ::: "memory")
#define CP_WAIT(n)  asm volatile("cp.async.wait_group %0;" :: "n"(n) : "memory")

// ============== cp.async 3-buffer fp16 batched GEMM (fp32 accum) ===========
// C[r] slab = A @ Bt[r, n0:n0+BN]^T.  BN=64 everywhere: acc=32 regs/thread
// -> 3 CTAs/SM (RF). blockIdx = (relation, m-tile, n-half of NTOT).
// mma m16n8k16; 8 warps 4(M) x 2(N); PAD2=40 conflict-free ldmatrix rows.
template<int BN, int Kdim, int NTOT>
__global__ __launch_bounds__(256, 3)
void rgemm_h(const __half* __restrict__ A, const __half* __restrict__ Bt,
             uint32_t* __restrict__ C) {
    constexpr int BM = 128, BK = 32, PAD2 = 40;
    constexpr int NCH = Kdim / BK;
    constexpr int WN = BN / 2, NT = WN / 8, NP = NT / 2;
    constexpr int ASTR = BM * PAD2;
    constexpr int BSTR = BN * PAD2;

    extern __shared__ __align__(16) __half smh[];
    __half* Asm = smh;                       // [3][BM][PAD2]
    __half* Bsm = smh + 3 * ASTR;            // [3][BN][PAD2]

    const int r   = blockIdx.x;
    const int m0  = blockIdx.y * BM;
    const int n0  = blockIdx.z * BN;
    const int tid = threadIdx.x;
    const int lane = tid & 31, wid = tid >> 5;
    const int mi = wid & 3, ni = wid >> 2;
    const int g = lane >> 2, t = lane & 3;

    const __half* Ab = A + (size_t)m0 * Kdim;
    const __half* Bb = Bt + ((size_t)r * NTOT + n0) * Kdim;
    uint32_t*     Cr = C + (size_t)r * N_NODES * (NTOT / 2)
                         + (size_t)m0 * (NTOT / 2) + n0 / 2;

    const int j8 = lane >> 3, i8 = lane & 7;
    uint32_t aAddr[2];
#pragma unroll
    for (int mt = 0; mt < 2; mt++) {
        int row = mi * 32 + mt * 16 + (j8 & 1) * 8 + i8;
        aAddr[mt] = smem_u32(&Asm[row * PAD2]) + (j8 >> 1) * 16;
    }
    uint32_t bAddr[NP];
#pragma unroll
    for (int p = 0; p < NP; p++) {
        int nrow = ni * WN + p * 16 + (j8 >> 1) * 8 + i8;
        bAddr[p] = smem_u32(&Bsm[nrow * PAD2]) + (j8 & 1) * 16;
    }

    auto load_stage = [&](int c, int s) {
        __half* Ad = Asm + s * ASTR;
#pragma unroll
        for (int i = 0; i < 2; i++) {
            int idx = i * 256 + tid;
            int row = idx >> 2, ch = (idx & 3) * 8;
            CP_ASYNC16(smem_u32(Ad + row * PAD2 + ch),
                       Ab + (size_t)row * Kdim + c * BK + ch);
        }
        __half* Bd = Bsm + s * BSTR;
        {   // BN=64: 256 chunks, one per thread
            int row = tid >> 2, ch = (tid & 3) * 8;
            CP_ASYNC16(smem_u32(Bd + row * PAD2 + ch),
                       Bb + (size_t)row * Kdim + c * BK + ch);
        }
        CP_COMMIT();
    };

    float acc[2][NT][4];
#pragma unroll
    for (int mt = 0; mt < 2; mt++)
#pragma unroll
        for (int nt = 0; nt < NT; nt++)
#pragma unroll
            for (int q = 0; q < 4; q++) acc[mt][nt][q] = 0.f;

    load_stage(0, 0);
    load_stage(1, 1);

    for (int c = 0; c < NCH; c++) {
        const int s = c % 3;
        CP_WAIT(1);
        __syncthreads();
        if (c + 2 < NCH) load_stage(c + 2, (c + 2) % 3);
        else CP_COMMIT();

        const uint32_t ao = (uint32_t)s * ASTR * 2, bo = (uint32_t)s * BSTR * 2;
#pragma unroll
        for (int kk = 0; kk < 2; kk++) {
            uint32_t a[2][4];
            ldsm_x4(a[0], aAddr[0] + ao + kk * 32);
            ldsm_x4(a[1], aAddr[1] + ao + kk * 32);
#pragma unroll
            for (int p = 0; p < NP; p++) {
                uint32_t b[4];
                ldsm_x4(b, bAddr[p] + bo + kk * 32);
#pragma unroll
                for (int mt = 0; mt < 2; mt++) {
                    mma_f16(acc[mt][2 * p],     a[mt], b[0], b[1]);
                    mma_f16(acc[mt][2 * p + 1], a[mt], b[2], b[3]);
                }
            }
        }
    }

    // ---- epilogue: pack adjacent cols as f16x2, store u32 ----
#pragma unroll
    for (int mt = 0; mt < 2; mt++) {
        int row = mi * 32 + mt * 16 + g;
#pragma unroll
        for (int nt = 0; nt < NT; nt++) {
            int col2 = (ni * WN + nt * 8) / 2 + t;
            Cr[(size_t)row * (NTOT / 2) + col2] =
                pack_f16x2(acc[mt][nt][0], acc[mt][nt][1]);
            Cr[(size_t)(row + 8) * (NTOT / 2) + col2] =
                pack_f16x2(acc[mt][nt][2], acc[mt][nt][3]);
        }
    }
}

// ---------------- pre-pass: fp32 -> fp16 (b_z) ------------------------------
__global__ void f32_to_f16(const float* __restrict__ src,
                           uint32_t* __restrict__ dst, size_t n8) {
    size_t i = (size_t)blockIdx.x * blockDim.x + threadIdx.x;
    if (i >= n8) return;
    float4 v0 = *(const float4*)(src + i * 8);
    float4 v1 = *(const float4*)(src + i * 8 + 4);
    uint4 o;
    o.x = pack_f16x2(v0.x, v0.y);
    o.y = pack_f16x2(v0.z, v0.w);
    o.z = pack_f16x2(v1.x, v1.y);
    o.w = pack_f16x2(v1.z, v1.w);
    *(uint4*)(dst + i * 4) = o;
}

// W[r][k][n] -> Wt[r][n][k], fp16
template<int K, int N>
__global__ void transpose_w(const float* __restrict__ W,
                            __half* __restrict__ Wt) {
    int r = blockIdx.y;
    int idx = blockIdx.x * 256 + threadIdx.x;
    if (idx >= K * N) return;
    int k = idx / N, n = idx % N;
    Wt[((size_t)r * N + n) * K + k] = __float2half_rn(W[((size_t)r * K + k) * N + n]);
}

// ================= CSR build (by dst) =======================================
__global__ void csr_zero() {
    int i = blockIdx.x * 256 + threadIdx.x;
    if (i < N_NODES) { g_deg[i] = 0; g_fil[i] = 0; }
}

__global__ void csr_count(const int* __restrict__ eidx) {
    int e = blockIdx.x * 256 + threadIdx.x;
    if (e < N_EDGES) atomicAdd(&g_deg[eidx[N_EDGES + e]], 1);
}

__global__ void scan_blocks() {
    __shared__ int s[256];
    int i = blockIdx.x * 256 + threadIdx.x;
    int v = g_deg[i];
    s[threadIdx.x] = v; __syncthreads();
    for (int d = 1; d < 256; d <<= 1) {
        int x = (threadIdx.x >= d) ? s[threadIdx.x - d] : 0;
        __syncthreads();
        s[threadIdx.x] += x;
        __syncthreads();
    }
    g_off[i] = s[threadIdx.x] - v;
    if (threadIdx.x == 255) g_bsum[blockIdx.x] = s[255];
}

__global__ void scan_tops() {
    __shared__ int s[512];
    int t = threadIdx.x;
    int v = (t < 400) ? g_bsum[t] : 0;
    s[t] = v; __syncthreads();
    for (int d = 1; d < 512; d <<= 1) {
        int x = (t >= d) ? s[t - d] : 0;
        __syncthreads();
        s[t] += x;
        __syncthreads();
    }
    if (t < 400) g_bsum[t] = s[t] - v;
    if (t == 0) g_off[N_NODES] = N_EDGES;
}

__global__ void scan_add() {
    int i = blockIdx.x * 256 + threadIdx.x;
    g_off[i] += g_bsum[blockIdx.x];
}

__global__ void csr_fill(const int* __restrict__ eidx,
                         const float* __restrict__ ew,
                         const int* __restrict__ et) {
    int e = blockIdx.x * 256 + threadIdx.x;
    if (e >= N_EDGES) return;
    int src = eidx[e], dst = eidx[N_EDGES + e], t = et[e];
    int pos = g_off[dst] + atomicAdd(&g_fil[dst], 1);
    g_epk[pos] = make_uint2((uint32_t)src | ((uint32_t)t << 20),
                            __float_as_uint(ew[e]));
}

// ===== CSR gather-aggregate (fp16 xw -> fp16 h), 2x unrolled ===============
// D/8 lanes per node; each lane owns 8 feats = one uint4 (4x f16x2).
template<int D>
__global__ void agg_csr(const uint32_t* __restrict__ xw,
                        const float* __restrict__ bias,
                        uint32_t* __restrict__ hout) {
    constexpr int L = D / 8;
    int gt = blockIdx.x * blockDim.x + threadIdx.x;
    int node = gt / L;
    int sub  = gt % L;
    if (node >= N_NODES) return;
    int beg = g_off[node], end = g_off[node + 1];

    float acc[8];
#pragma unroll
    for (int q = 0; q < 8; q++) acc[q] = 0.f;

    const uint4* xw4 = (const uint4*)xw;
    int j = beg;
    for (; j + 2 <= end; j += 2) {
        uint2 e0 = g_epk[j], e1 = g_epk[j + 1];
        uint4 v0 = xw4[((size_t)(e0.x >> 20) * N_NODES + (e0.x & 0xFFFFF)) * (D / 8) + sub];
        uint4 v1 = xw4[((size_t)(e1.x >> 20) * N_NODES + (e1.x & 0xFFFFF)) * (D / 8) + sub];
        float w0 = __uint_as_float(e0.y), w1 = __uint_as_float(e1.y);
        float2 f;
        f = unpack_f16x2(v0.x); acc[0] += f.x * w0; acc[1] += f.y * w0;
        f = unpack_f16x2(v0.y); acc[2] += f.x * w0; acc[3] += f.y * w0;
        f = unpack_f16x2(v0.z); acc[4] += f.x * w0; acc[5] += f.y * w0;
        f = unpack_f16x2(v0.w); acc[6] += f.x * w0; acc[7] += f.y * w0;
        f = unpack_f16x2(v1.x); acc[0] += f.x * w1; acc[1] += f.y * w1;
        f = unpack_f16x2(v1.y); acc[2] += f.x * w1; acc[3] += f.y * w1;
        f = unpack_f16x2(v1.z); acc[4] += f.x * w1; acc[5] += f.y * w1;
        f = unpack_f16x2(v1.w); acc[6] += f.x * w1; acc[7] += f.y * w1;
    }
    if (j < end) {
        uint2 e0 = g_epk[j];
        uint4 v0 = xw4[((size_t)(e0.x >> 20) * N_NODES + (e0.x & 0xFFFFF)) * (D / 8) + sub];
        float w0 = __uint_as_float(e0.y);
        float2 f;
        f = unpack_f16x2(v0.x); acc[0] += f.x * w0; acc[1] += f.y * w0;
        f = unpack_f16x2(v0.y); acc[2] += f.x * w0; acc[3] += f.y * w0;
        f = unpack_f16x2(v0.z); acc[4] += f.x * w0; acc[5] += f.y * w0;
        f = unpack_f16x2(v0.w); acc[6] += f.x * w0; acc[7] += f.y * w0;
    }
    float4 b0 = *(const float4*)&bias[sub * 8];
    float4 b1 = *(const float4*)&bias[sub * 8 + 4];
    uint4 o;
    o.x = pack_f16x2(fmaxf(acc[0] + b0.x, 0.f), fmaxf(acc[1] + b0.y, 0.f));
    o.y = pack_f16x2(fmaxf(acc[2] + b0.z, 0.f), fmaxf(acc[3] + b0.w, 0.f));
    o.z = pack_f16x2(fmaxf(acc[4] + b1.x, 0.f), fmaxf(acc[5] + b1.y, 0.f));
    o.w = pack_f16x2(fmaxf(acc[6] + b1.z, 0.f), fmaxf(acc[7] + b1.w, 0.f));
    *(uint4*)&hout[(size_t)node * (D / 2) + sub * 4] = o;
}

// layer 3: lane-per-edge + warp reduce (no relu on output)
__global__ void agg_out(const float* __restrict__ xw3,
                        const float* __restrict__ b3,
                        float* __restrict__ out) {
    int node = (blockIdx.x * blockDim.x + threadIdx.x) >> 5;
    int lane = threadIdx.x & 31;
    if (node >= N_NODES) return;
    int beg = g_off[node], end = g_off[node + 1];
    float s = 0.f;
    for (int j = beg + lane; j < end; j += 32) {
        uint2 e = g_epk[j];
        s += xw3[(size_t)(e.x >> 20) * N_NODES + (e.x & 0xFFFFF)]
             * __uint_as_float(e.y);
    }
#pragma unroll
    for (int o = 16; o; o >>= 1) s += __shfl_down_sync(0xffffffff, s, o);
    if (lane == 0) out[node] = s + b3[0];
}

// ---------------- layer-3 transform: xw3[r,n] = h2[n] . W3[r] (h2 fp16) ----
__global__ void gemm3_kernel(const uint32_t* __restrict__ h2,
                             const float* __restrict__ W3,
                             float* __restrict__ xw3) {
    __shared__ float w[N_REL][D2];
    for (int i = threadIdx.x; i < N_REL * D2; i += blockDim.x)
        w[i / D2][i % D2] = W3[i];
    __syncthreads();

    int n = blockIdx.x * blockDim.x + threadIdx.x;
    if (n >= N_NODES) return;

    float acc[N_REL];
#pragma unroll
    for (int r = 0; r < N_REL; r++) acc[r] = 0.f;

    const uint32_t* hp = &h2[(size_t)n * (D2 / 2)];
#pragma unroll
    for (int k2 = 0; k2 < D2 / 2; k2++) {
        float2 f = unpack_f16x2(hp[k2]);
#pragma unroll
        for (int r = 0; r < N_REL; r++) {
            acc[r] += f.x * w[r][k2 * 2 + 0];
            acc[r] += f.y * w[r][k2 * 2 + 1];
        }
    }
#pragma unroll
    for (int r = 0; r < N_REL; r++)
        xw3[(size_t)r * N_NODES + n] = acc[r];
}

// ---------------- launcher --------------------------------------------------
extern "C" void kernel_launch(void* const* d_in, const int* in_sizes, int n_in,
                              void* d_out, int out_size) {
    const float* b_z  = (const float*)d_in[0];
    const int*   eidx = (const int*)d_in[1];
    const float* ew   = (const float*)d_in[2];
    const int*   et   = (const int*)d_in[3];
    const float* W1   = (const float*)d_in[4];
    const float* b1   = (const float*)d_in[5];
    const float* W2   = (const float*)d_in[6];
    const float* b2   = (const float*)d_in[7];
    const float* W3   = (const float*)d_in[8];
    const float* b3   = (const float*)d_in[9];
    float*       out  = (float*)d_out;

    void* p;
    __half *a1h, *w1t, *w2t;
    uint32_t *xw1, *xw2, *h1, *h2;
    float *xw3;
    cudaGetSymbolAddress(&p, g_a1h); a1h = (__half*)p;
    cudaGetSymbolAddress(&p, g_xw1); xw1 = (uint32_t*)p;
    cudaGetSymbolAddress(&p, g_h1 ); h1  = (uint32_t*)p;
    cudaGetSymbolAddress(&p, g_xw2); xw2 = (uint32_t*)p;
    cudaGetSymbolAddress(&p, g_h2 ); h2  = (uint32_t*)p;
    cudaGetSymbolAddress(&p, g_xw3); xw3 = (float*)p;
    cudaGetSymbolAddress(&p, g_w1t); w1t = (__half*)p;
    cudaGetSymbolAddress(&p, g_w2t); w2t = (__half*)p;

    const int smemg = 3 * (128 + 64) * 40 * 2;   // 46080
    cudaFuncSetAttribute(rgemm_h<64, 256, 128>,
                         cudaFuncAttributeMaxDynamicSharedMemorySize, smemg);
    cudaFuncSetAttribute(rgemm_h<64, 128, 64>,
                         cudaFuncAttributeMaxDynamicSharedMemorySize, smemg);

    // ---- CSR build (by dst) + input/weight conversion ----
    csr_zero<<<400, 256>>>();
    csr_count<<<N_EDGES / 256, 256>>>(eidx);
    scan_blocks<<<400, 256>>>();
    scan_tops<<<1, 512>>>();
    scan_add<<<400, 256>>>();
    csr_fill<<<N_EDGES / 256, 256>>>(eidx, ew, et);
    f32_to_f16<<<(int)(((size_t)N_NODES * D0 / 8 + 255) / 256), 256>>>(
        b_z, (uint32_t*)a1h, (size_t)N_NODES * D0 / 8);
    transpose_w<D0, D1><<<dim3((D0 * D1 + 255) / 256, N_REL), 256>>>(W1, w1t);
    transpose_w<D1, D2><<<dim3((D1 * D2 + 255) / 256, N_REL), 256>>>(W2, w2t);

    // ---- layer 1: xw1[r] = a1h @ w1t[r]^T (fp16); h1 = relu(b1 + agg) ----
    rgemm_h<64, 256, 128>
        <<<dim3(N_REL, N_NODES / 128, 2), 256, smemg>>>(a1h, w1t, xw1);
    agg_csr<D1><<<N_NODES * (D1 / 8) / 256, 256>>>(xw1, b1, h1);

    // ---- layer 2: xw2[r] = h1 @ w2t[r]^T (fp16); h2 = relu(b2 + agg) ----
    rgemm_h<64, 128, 64>
        <<<dim3(N_REL, N_NODES / 128, 1), 256, smemg>>>((const __half*)h1, w2t, xw2);
    agg_csr<D2><<<N_NODES * (D2 / 8) / 256, 256>>>(xw2, b2, h2);

    // ---- layer 3: xw3[r,n] = h2[n] . W3[r]; out = b3 + aggregate ----
    gemm3_kernel<<<(N_NODES + 255) / 256, 256>>>(h2, W3, xw3);
    agg_out<<<N_NODES * 32 / 256, 256>>>(xw3, b3, out);
}